// round 8
// baseline (speedup 1.0000x reference)
#include <cuda_runtime.h>

// DeepAR forward: 2-layer LSTM (H=64), T=383 steps, 16384 independent seqs.
// Persistent: 296 CTAs (2 full waves) x 256 threads, 56 seqs/CTA.
// R8: all lane-duplicated scalar arithmetic moved onto packed f32x2
// (cell updates + pre0 x-projection via transposed x staging); h-state
// stores inlined into the interleaved j-loops. Same algorithm/precision.

#define TPB 256
#define SEQ 56          // sequences per CTA (4 groups x 14)
#define GRP 14
#define NPAIR 7         // seq pairs per thread
#define NCTA 296        // 2 x 148 -> two full waves
#define NSTEP 383
#define NSEQ_TOT 16384
#define HP 58           // h / xT row pitch (even -> 8B-aligned pairs)
#define XSBUF (5 * HP)  // one x staging buffer: 5 rows x HP

// shared layout (floats)
#define OFF_WT0 0               // [64][64] float4 quads   16384
#define OFF_WT1 16384           // [128][64] float4 quads  32768
#define OFF_H0  49152           // [64][HP]                 3712
#define OFF_H1  52864           // [64][HP]                 3712
#define OFF_XS  56576           // 2 x [5][HP] transposed    580
#define OFF_HW  57156           // head_W (2x64)             128
#define OFF_HB  57284           // head_b                      2
#define SM_FLOATS 57286
#define SM_BYTES (SM_FLOATS * 4)

typedef unsigned long long ull;

static __device__ __forceinline__ ull pk2(float a, float b) {
    ull r; asm("mov.b64 %0, {%1, %2};" : "=l"(r) : "f"(a), "f"(b)); return r;
}
static __device__ __forceinline__ void upk2(ull v, float& a, float& b) {
    asm("mov.b64 {%0, %1}, %2;" : "=f"(a), "=f"(b) : "l"(v));
}
static __device__ __forceinline__ ull fma2(ull a, ull b, ull c) {
    ull d; asm("fma.rn.f32x2 %0, %1, %2, %3;" : "=l"(d) : "l"(a), "l"(b), "l"(c)); return d;
}
static __device__ __forceinline__ ull mul2(ull a, ull b) {
    ull d; asm("mul.rn.f32x2 %0, %1, %2;" : "=l"(d) : "l"(a), "l"(b)); return d;
}
static __device__ __forceinline__ ull add2(ull a, ull b) {
    ull d; asm("add.rn.f32x2 %0, %1, %2;" : "=l"(d) : "l"(a), "l"(b)); return d;
}
static __device__ __forceinline__ float ex2_(float x) {
    float r; asm("ex2.approx.f32 %0, %1;" : "=f"(r) : "f"(x)); return r;
}
static __device__ __forceinline__ float rcp_(float x) {
    float r; asm("rcp.approx.f32 %0, %1;" : "=f"(r) : "f"(x)); return r;
}

// packed sigmoid: rcp(1 + exp2(x * -log2e)) per lane
static __device__ __forceinline__ ull sig2(ull x, ull NL2E2, ull ONE2) {
    ull m = mul2(x, NL2E2);
    float m0, m1; upk2(m, m0, m1);
    ull d = add2(pk2(ex2_(m0), ex2_(m1)), ONE2);
    float d0, d1; upk2(d, d0, d1);
    return pk2(rcp_(d0), rcp_(d1));
}
// packed tanh: 1 - 2*rcp(1 + exp2(x * 2log2e)); exact at saturation
static __device__ __forceinline__ ull tanh2(ull x, ull TL2E2, ull ONE2, ull NTWO2) {
    ull m = mul2(x, TL2E2);
    float m0, m1; upk2(m, m0, m1);
    ull d = add2(pk2(ex2_(m0), ex2_(m1)), ONE2);
    float d0, d1; upk2(d, d0, d1);
    return fma2(pk2(rcp_(d0), rcp_(d1)), NTWO2, ONE2);
}

// packed LSTM cell update for one pair; writes new h (packed) to smem.
#define CELL2(acc, cp, p, dst) do {                                           \
    ull si_ = sig2(acc[0][p], NL2E2, ONE2);                                   \
    ull sf_ = sig2(acc[1][p], NL2E2, ONE2);                                   \
    ull tg_ = tanh2(acc[2][p], TL2E2, ONE2, NTWO2);                           \
    ull so_ = sig2(acc[3][p], NL2E2, ONE2);                                   \
    cp[p] = fma2(sf_, cp[p], mul2(si_, tg_));                                 \
    *(ull*)(dst) = mul2(so_, tanh2(cp[p], TL2E2, ONE2, NTWO2));               \
} while (0)

// plain matvec: acc[g][p] += Wq[j][u].{xyzw} * h[j][pair p]
static __device__ __forceinline__ void mv64(ull (&acc)[4][NPAIR],
                                            const float4* __restrict__ Wq,
                                            const float* __restrict__ H,
                                            int u) {
#pragma unroll 8
    for (int j = 0; j < 64; j++) {
        float4 w = Wq[j * 64 + u];
        ull W0 = pk2(w.x, w.x), W1 = pk2(w.y, w.y);
        ull W2 = pk2(w.z, w.z), W3 = pk2(w.w, w.w);
        const ull* hr = (const ull*)(H + j * HP);
#pragma unroll
        for (int p = 0; p < NPAIR; p++) {
            ull h = hr[p];
            acc[0][p] = fma2(W0, h, acc[0][p]);
            acc[1][p] = fma2(W1, h, acc[1][p]);
            acc[2][p] = fma2(W2, h, acc[2][p]);
            acc[3][p] = fma2(W3, h, acc[3][p]);
        }
    }
}

// packed x-projection: acc[g][p] += v1*prev + wc.cov  (x transposed [k][s])
static __device__ __forceinline__ void xpart(ull (&acc)[4][NPAIR],
                                             const float* __restrict__ xb,
                                             const float* v1r,
                                             const float (*wcr)[4]) {
    ull v1d[4], wcd[4][4];
#pragma unroll
    for (int g = 0; g < 4; g++) {
        v1d[g] = pk2(v1r[g], v1r[g]);
#pragma unroll
        for (int k = 0; k < 4; k++) wcd[g][k] = pk2(wcr[g][k], wcr[g][k]);
    }
#pragma unroll
    for (int p = 0; p < NPAIR; p++) {
        ull x0 = *(const ull*)(xb + 2 * p);
        ull x1 = *(const ull*)(xb + HP + 2 * p);
        ull x2 = *(const ull*)(xb + 2 * HP + 2 * p);
        ull x3 = *(const ull*)(xb + 3 * HP + 2 * p);
        ull x4 = *(const ull*)(xb + 4 * HP + 2 * p);
#pragma unroll
        for (int g = 0; g < 4; g++) {
            ull a = acc[g][p];
            a = fma2(x0, v1d[g], a);
            a = fma2(x1, wcd[g][0], a);
            a = fma2(x2, wcd[g][1], a);
            a = fma2(x3, wcd[g][2], a);
            a = fma2(x4, wcd[g][3], a);
            acc[g][p] = a;
        }
    }
}

// x-fetch: prev target at time t, covariates at time t+1
static __device__ __forceinline__ void ldx(const float* __restrict__ hist,
                                           const float* __restrict__ fut,
                                           int myb, int myn, int t,
                                           float& x0, float& x1, float& x2,
                                           float& x3, float& x4) {
    const float* s1 = (t < 336)
        ? hist + (((size_t)myb * 336 + t) * 512 + myn) * 5
        : fut  + (((size_t)myb * 48 + (t - 336)) * 512 + myn) * 5;
    int tc = t + 1;
    const float* s2 = (tc < 336)
        ? hist + (((size_t)myb * 336 + tc) * 512 + myn) * 5
        : fut  + (((size_t)myb * 48 + (tc - 336)) * 512 + myn) * 5;
    x0 = s1[0];
    x1 = s2[1]; x2 = s2[2]; x3 = s2[3]; x4 = s2[4];
}

extern "C" __global__ void __launch_bounds__(TPB, 1)
deepar_kernel(const float* __restrict__ hist,   // (32,336,512,5)
              const float* __restrict__ fut,    // (32, 48,512,5)
              const float* __restrict__ emb_W,  // (32,1)
              const float* __restrict__ emb_b,  // (32)
              const float* __restrict__ W_ih0,  // (256,36)
              const float* __restrict__ W_hh0,  // (256,64)
              const float* __restrict__ b_ih0,
              const float* __restrict__ b_hh0,
              const float* __restrict__ W_ih1,  // (256,64)
              const float* __restrict__ W_hh1,  // (256,64)
              const float* __restrict__ b_ih1,
              const float* __restrict__ b_hh1,
              const float* __restrict__ head_W, // (2,64)
              const float* __restrict__ head_b, // (2)
              float* __restrict__ out)          // (32,48,512,2)
{
    extern __shared__ float sm[];
    float4* Wt0q = (float4*)(sm + OFF_WT0);
    float4* Wt1q = (float4*)(sm + OFF_WT1);   // [0..63]=W_ih1, [64..127]=W_hh1
    float* h0T = sm + OFF_H0;
    float* h1T = sm + OFF_H1;
    float* xsT = sm + OFF_XS;                 // two [5][HP] buffers
    float* hw  = sm + OFF_HW;
    float* hb  = sm + OFF_HB;

    const int tid = threadIdx.x;
    const int u = tid & 63;
    const int sg = tid >> 6;
    const int sbase = sg * GRP;               // even -> 8B-aligned pairs
    const int gbase = blockIdx.x * SEQ;

    const ull ONE2  = pk2(1.f, 1.f);
    const ull NTWO2 = pk2(-2.f, -2.f);
    const ull NL2E2 = pk2(-1.4426950408889634f, -1.4426950408889634f);
    const ull TL2E2 = pk2(2.8853900817779268f, 2.8853900817779268f);

    // ---- weights -> smem as per-unit gate quads ----
    for (int e = tid; e < 64 * 64; e += TPB) {
        int j = e >> 6, uu = e & 63;
        Wt0q[j * 64 + uu] = make_float4(W_hh0[uu * 64 + j],
                                        W_hh0[(64 + uu) * 64 + j],
                                        W_hh0[(128 + uu) * 64 + j],
                                        W_hh0[(192 + uu) * 64 + j]);
    }
    for (int e = tid; e < 128 * 64; e += TPB) {
        int j = e >> 6, uu = e & 63;
        const float* src = (j < 64) ? (W_ih1 + j) : (W_hh1 + (j - 64));
        Wt1q[j * 64 + uu] = make_float4(src[uu * 64],
                                        src[(64 + uu) * 64],
                                        src[(128 + uu) * 64],
                                        src[(192 + uu) * 64]);
    }
    for (int e = tid; e < 64 * HP; e += TPB) { h0T[e] = 0.f; h1T[e] = 0.f; }
    if (tid < 128) hw[tid] = head_W[tid];
    if (tid < 2)   hb[tid] = head_b[tid];

    // ---- fold rank-1 embedding into per-gate scalar coefficients ----
    float v1r[4], v2r[4], wcr[4][4], b1r[4];
#pragma unroll
    for (int g = 0; g < 4; g++) {
        int r = g * 64 + u;
        const float* wr = W_ih0 + r * 36;
        float a = 0.f, bb = 0.f;
#pragma unroll
        for (int e = 0; e < 32; e++) {
            a  = fmaf(wr[e], emb_W[e], a);
            bb = fmaf(wr[e], emb_b[e], bb);
        }
        v1r[g] = a;
        v2r[g] = bb + b_ih0[r] + b_hh0[r];
#pragma unroll
        for (int k = 0; k < 4; k++) wcr[g][k] = wr[32 + k];
        b1r[g] = b_ih1[r] + b_hh1[r];
    }

    ull c0p[NPAIR], c1p[NPAIR];
#pragma unroll
    for (int i = 0; i < NPAIR; i++) { c0p[i] = 0ull; c1p[i] = 0ull; }

    const bool duty = (u < GRP);
    const int mys = sbase + (u < GRP ? u : 0);
    int mygs = gbase + mys; if (mygs > NSEQ_TOT - 1) mygs = NSEQ_TOT - 1;
    const int myb = mygs >> 9, myn = mygs & 511;

    const int hb0 = u * HP + sbase;   // this thread's h row base (both layers)

    // ---- prologue: stage x(0) transposed into buf0; prefetch x(1) ----
    float xr0, xr1, xr2, xr3, xr4;
    if (duty) {
        float a0, a1, a2, a3, a4;
        ldx(hist, fut, myb, myn, 0, a0, a1, a2, a3, a4);
        float* xp = xsT + mys;        // column mys of buf0
        xp[0] = a0; xp[HP] = a1; xp[2 * HP] = a2; xp[3 * HP] = a3; xp[4 * HP] = a4;
        ldx(hist, fut, myb, myn, 1, xr0, xr1, xr2, xr3, xr4);
    }
    __syncthreads();   // weights, zero h, x(0) visible

    // acc0(0) = v2 + x(0)-part (h0 is zero -> matvec contributes nothing)
    ull acc0[4][NPAIR];
    {
        ull v2d[4];
#pragma unroll
        for (int g = 0; g < 4; g++) v2d[g] = pk2(v2r[g], v2r[g]);
#pragma unroll
        for (int p = 0; p < NPAIR; p++)
#pragma unroll
            for (int g = 0; g < 4; g++) acc0[g][p] = v2d[g];
        xpart(acc0, xsT + sbase, v1r, wcr);
    }

    for (int t = 0; t < NSTEP; t++) {
        const bool notlast = (t + 1 < NSTEP);

        // ---- phase 1: accB = b1 + W_hh1 @ h1_old, interleaved with packed
        //      U0(t) cell updates; h0(t) stores inlined (h0T free post-bar2).
        ull accB[4][NPAIR];
        {
            ull b1d[4];
#pragma unroll
            for (int g = 0; g < 4; g++) b1d[g] = pk2(b1r[g], b1r[g]);
#pragma unroll
            for (int p = 0; p < NPAIR; p++)
#pragma unroll
                for (int g = 0; g < 4; g++) accB[g][p] = b1d[g];
        }
        {
            const float4* Wq = Wt1q + 64 * 64;   // W_hh1 quads
            const float* H = h1T + sbase;
#pragma unroll
            for (int j = 0; j < 64; j++) {
                float4 w = Wq[j * 64 + u];
                ull W0 = pk2(w.x, w.x), W1 = pk2(w.y, w.y);
                ull W2 = pk2(w.z, w.z), W3 = pk2(w.w, w.w);
                const ull* hr = (const ull*)(H + j * HP);
#pragma unroll
                for (int p = 0; p < NPAIR; p++) {
                    ull h = hr[p];
                    accB[0][p] = fma2(W0, h, accB[0][p]);
                    accB[1][p] = fma2(W1, h, accB[1][p]);
                    accB[2][p] = fma2(W2, h, accB[2][p]);
                    accB[3][p] = fma2(W3, h, accB[3][p]);
                }
                if ((j & 7) == 1) {               // j=1,9,..,49 -> p=0..6
                    const int p = j >> 3;
                    if (p < NPAIR) CELL2(acc0, c0p, p, h0T + hb0 + 2 * p);
                }
            }
        }

        // ---- phase 2: stage x(t+1) transposed; bar1 ----
        if (duty && notlast) {
            float* xp = xsT + ((t + 1) & 1) * XSBUF + mys;
            xp[0] = xr0; xp[HP] = xr1; xp[2 * HP] = xr2;
            xp[3 * HP] = xr3; xp[4 * HP] = xr4;
        }
        __syncthreads();   // bar1: h0(t), x(t+1) visible; h1_old reads done

        // prefetch x(t+2) (latency hidden under phases 3-4)
        if (duty && t + 2 < NSTEP)
            ldx(hist, fut, myb, myn, t + 2, xr0, xr1, xr2, xr3, xr4);

        // ---- phase 3: accB += W_ih1 @ h0(t) ----
        mv64(accB, Wt1q, h0T + sbase, u);

        // ---- phase 4: U1(t) interleaved with acc0(t+1) matvec; inline h1
        //      stores; then packed x(t+1)-projection (accB dead by then).
        if (notlast) {
            {
                ull v2d[4];
#pragma unroll
                for (int g = 0; g < 4; g++) v2d[g] = pk2(v2r[g], v2r[g]);
#pragma unroll
                for (int p = 0; p < NPAIR; p++)
#pragma unroll
                    for (int g = 0; g < 4; g++) acc0[g][p] = v2d[g];
            }
            const float* H0 = h0T + sbase;
#pragma unroll
            for (int j = 0; j < 64; j++) {
                float4 w = Wt0q[j * 64 + u];
                ull W0 = pk2(w.x, w.x), W1 = pk2(w.y, w.y);
                ull W2 = pk2(w.z, w.z), W3 = pk2(w.w, w.w);
                const ull* hr = (const ull*)(H0 + j * HP);
#pragma unroll
                for (int p = 0; p < NPAIR; p++) {
                    ull h = hr[p];
                    acc0[0][p] = fma2(W0, h, acc0[0][p]);
                    acc0[1][p] = fma2(W1, h, acc0[1][p]);
                    acc0[2][p] = fma2(W2, h, acc0[2][p]);
                    acc0[3][p] = fma2(W3, h, acc0[3][p]);
                }
                if ((j & 7) == 1) {
                    const int p = j >> 3;
                    if (p < NPAIR) CELL2(accB, c1p, p, h1T + hb0 + 2 * p);
                }
            }
            xpart(acc0, xsT + ((t + 1) & 1) * XSBUF + sbase, v1r, wcr);
        } else {
#pragma unroll
            for (int p = 0; p < NPAIR; p++)
                CELL2(accB, c1p, p, h1T + hb0 + 2 * p);
        }
        __syncthreads();   // bar2: h1(t) visible

        // ---- head (last 48 steps; duty threads, 1 seq each) ----
        if (t >= 335 && duty) {
            float p0 = hb[0], p1 = hb[1];
#pragma unroll 8
            for (int j = 0; j < 64; j++) {
                float v = fmaxf(h1T[j * HP + mys], 0.f);
                p0 = fmaf(v, hw[j], p0);
                p1 = fmaf(v, hw[64 + j], p1);
            }
            float sp = (p1 > 15.f) ? p1 : log1pf(__expf(p1));
            ((float2*)out)[((size_t)myb * 48 + (t - 335)) * 512 + myn] =
                make_float2(p0, sp);
        }
        // h1T next overwritten in phase 4 of t+1 (after bar1) -> head safe
    }
}

extern "C" void kernel_launch(void* const* d_in, const int* in_sizes, int n_in,
                              void* d_out, int out_size) {
    (void)in_sizes; (void)n_in; (void)out_size;
    const float* hist   = (const float*)d_in[0];
    const float* fut    = (const float*)d_in[1];
    const float* emb_W  = (const float*)d_in[2];
    const float* emb_b  = (const float*)d_in[3];
    const float* W_ih0  = (const float*)d_in[4];
    const float* W_hh0  = (const float*)d_in[5];
    const float* b_ih0  = (const float*)d_in[6];
    const float* b_hh0  = (const float*)d_in[7];
    const float* W_ih1  = (const float*)d_in[8];
    const float* W_hh1  = (const float*)d_in[9];
    const float* b_ih1  = (const float*)d_in[10];
    const float* b_hh1  = (const float*)d_in[11];
    const float* head_W = (const float*)d_in[12];
    const float* head_b = (const float*)d_in[13];
    float* out = (float*)d_out;

    cudaFuncSetAttribute(deepar_kernel,
                         cudaFuncAttributeMaxDynamicSharedMemorySize, SM_BYTES);

    deepar_kernel<<<NCTA, TPB, SM_BYTES>>>(
        hist, fut, emb_W, emb_b,
        W_ih0, W_hh0, b_ih0, b_hh0,
        W_ih1, W_hh1, b_ih1, b_hh1,
        head_W, head_b, out);
}

// round 9
// speedup vs baseline: 1.0013x; 1.0013x over previous
#include <cuda_runtime.h>

// DeepAR forward: 2-layer LSTM (H=64), T=383 steps, 16384 independent seqs.
// Persistent: 296 CTAs (2 full waves) x 256 threads, 56 seqs/CTA.
// R8: all lane-duplicated scalar arithmetic moved onto packed f32x2
// (cell updates + pre0 x-projection via transposed x staging); h-state
// stores inlined into the interleaved j-loops. Same algorithm/precision.

#define TPB 256
#define SEQ 56          // sequences per CTA (4 groups x 14)
#define GRP 14
#define NPAIR 7         // seq pairs per thread
#define NCTA 296        // 2 x 148 -> two full waves
#define NSTEP 383
#define NSEQ_TOT 16384
#define HP 58           // h / xT row pitch (even -> 8B-aligned pairs)
#define XSBUF (5 * HP)  // one x staging buffer: 5 rows x HP

// shared layout (floats)
#define OFF_WT0 0               // [64][64] float4 quads   16384
#define OFF_WT1 16384           // [128][64] float4 quads  32768
#define OFF_H0  49152           // [64][HP]                 3712
#define OFF_H1  52864           // [64][HP]                 3712
#define OFF_XS  56576           // 2 x [5][HP] transposed    580
#define OFF_HW  57156           // head_W (2x64)             128
#define OFF_HB  57284           // head_b                      2
#define SM_FLOATS 57286
#define SM_BYTES (SM_FLOATS * 4)

typedef unsigned long long ull;

static __device__ __forceinline__ ull pk2(float a, float b) {
    ull r; asm("mov.b64 %0, {%1, %2};" : "=l"(r) : "f"(a), "f"(b)); return r;
}
static __device__ __forceinline__ void upk2(ull v, float& a, float& b) {
    asm("mov.b64 {%0, %1}, %2;" : "=f"(a), "=f"(b) : "l"(v));
}
static __device__ __forceinline__ ull fma2(ull a, ull b, ull c) {
    ull d; asm("fma.rn.f32x2 %0, %1, %2, %3;" : "=l"(d) : "l"(a), "l"(b), "l"(c)); return d;
}
static __device__ __forceinline__ ull mul2(ull a, ull b) {
    ull d; asm("mul.rn.f32x2 %0, %1, %2;" : "=l"(d) : "l"(a), "l"(b)); return d;
}
static __device__ __forceinline__ ull add2(ull a, ull b) {
    ull d; asm("add.rn.f32x2 %0, %1, %2;" : "=l"(d) : "l"(a), "l"(b)); return d;
}
static __device__ __forceinline__ float ex2_(float x) {
    float r; asm("ex2.approx.f32 %0, %1;" : "=f"(r) : "f"(x)); return r;
}
static __device__ __forceinline__ float rcp_(float x) {
    float r; asm("rcp.approx.f32 %0, %1;" : "=f"(r) : "f"(x)); return r;
}

// packed sigmoid: rcp(1 + exp2(x * -log2e)) per lane
static __device__ __forceinline__ ull sig2(ull x, ull NL2E2, ull ONE2) {
    ull m = mul2(x, NL2E2);
    float m0, m1; upk2(m, m0, m1);
    ull d = add2(pk2(ex2_(m0), ex2_(m1)), ONE2);
    float d0, d1; upk2(d, d0, d1);
    return pk2(rcp_(d0), rcp_(d1));
}
// packed tanh: 1 - 2*rcp(1 + exp2(x * 2log2e)); exact at saturation
static __device__ __forceinline__ ull tanh2(ull x, ull TL2E2, ull ONE2, ull NTWO2) {
    ull m = mul2(x, TL2E2);
    float m0, m1; upk2(m, m0, m1);
    ull d = add2(pk2(ex2_(m0), ex2_(m1)), ONE2);
    float d0, d1; upk2(d, d0, d1);
    return fma2(pk2(rcp_(d0), rcp_(d1)), NTWO2, ONE2);
}

// packed LSTM cell update for one pair; writes new h (packed) to smem.
#define CELL2(acc, cp, p, dst) do {                                           \
    ull si_ = sig2(acc[0][p], NL2E2, ONE2);                                   \
    ull sf_ = sig2(acc[1][p], NL2E2, ONE2);                                   \
    ull tg_ = tanh2(acc[2][p], TL2E2, ONE2, NTWO2);                           \
    ull so_ = sig2(acc[3][p], NL2E2, ONE2);                                   \
    cp[p] = fma2(sf_, cp[p], mul2(si_, tg_));                                 \
    *(ull*)(dst) = mul2(so_, tanh2(cp[p], TL2E2, ONE2, NTWO2));               \
} while (0)

// plain matvec: acc[g][p] += Wq[j][u].{xyzw} * h[j][pair p]
static __device__ __forceinline__ void mv64(ull (&acc)[4][NPAIR],
                                            const float4* __restrict__ Wq,
                                            const float* __restrict__ H,
                                            int u) {
#pragma unroll 8
    for (int j = 0; j < 64; j++) {
        float4 w = Wq[j * 64 + u];
        ull W0 = pk2(w.x, w.x), W1 = pk2(w.y, w.y);
        ull W2 = pk2(w.z, w.z), W3 = pk2(w.w, w.w);
        const ull* hr = (const ull*)(H + j * HP);
#pragma unroll
        for (int p = 0; p < NPAIR; p++) {
            ull h = hr[p];
            acc[0][p] = fma2(W0, h, acc[0][p]);
            acc[1][p] = fma2(W1, h, acc[1][p]);
            acc[2][p] = fma2(W2, h, acc[2][p]);
            acc[3][p] = fma2(W3, h, acc[3][p]);
        }
    }
}

// packed x-projection: acc[g][p] += v1*prev + wc.cov  (x transposed [k][s])
static __device__ __forceinline__ void xpart(ull (&acc)[4][NPAIR],
                                             const float* __restrict__ xb,
                                             const float* v1r,
                                             const float (*wcr)[4]) {
    ull v1d[4], wcd[4][4];
#pragma unroll
    for (int g = 0; g < 4; g++) {
        v1d[g] = pk2(v1r[g], v1r[g]);
#pragma unroll
        for (int k = 0; k < 4; k++) wcd[g][k] = pk2(wcr[g][k], wcr[g][k]);
    }
#pragma unroll
    for (int p = 0; p < NPAIR; p++) {
        ull x0 = *(const ull*)(xb + 2 * p);
        ull x1 = *(const ull*)(xb + HP + 2 * p);
        ull x2 = *(const ull*)(xb + 2 * HP + 2 * p);
        ull x3 = *(const ull*)(xb + 3 * HP + 2 * p);
        ull x4 = *(const ull*)(xb + 4 * HP + 2 * p);
#pragma unroll
        for (int g = 0; g < 4; g++) {
            ull a = acc[g][p];
            a = fma2(x0, v1d[g], a);
            a = fma2(x1, wcd[g][0], a);
            a = fma2(x2, wcd[g][1], a);
            a = fma2(x3, wcd[g][2], a);
            a = fma2(x4, wcd[g][3], a);
            acc[g][p] = a;
        }
    }
}

// x-fetch: prev target at time t, covariates at time t+1
static __device__ __forceinline__ void ldx(const float* __restrict__ hist,
                                           const float* __restrict__ fut,
                                           int myb, int myn, int t,
                                           float& x0, float& x1, float& x2,
                                           float& x3, float& x4) {
    const float* s1 = (t < 336)
        ? hist + (((size_t)myb * 336 + t) * 512 + myn) * 5
        : fut  + (((size_t)myb * 48 + (t - 336)) * 512 + myn) * 5;
    int tc = t + 1;
    const float* s2 = (tc < 336)
        ? hist + (((size_t)myb * 336 + tc) * 512 + myn) * 5
        : fut  + (((size_t)myb * 48 + (tc - 336)) * 512 + myn) * 5;
    x0 = s1[0];
    x1 = s2[1]; x2 = s2[2]; x3 = s2[3]; x4 = s2[4];
}

extern "C" __global__ void __launch_bounds__(TPB, 1)
deepar_kernel(const float* __restrict__ hist,   // (32,336,512,5)
              const float* __restrict__ fut,    // (32, 48,512,5)
              const float* __restrict__ emb_W,  // (32,1)
              const float* __restrict__ emb_b,  // (32)
              const float* __restrict__ W_ih0,  // (256,36)
              const float* __restrict__ W_hh0,  // (256,64)
              const float* __restrict__ b_ih0,
              const float* __restrict__ b_hh0,
              const float* __restrict__ W_ih1,  // (256,64)
              const float* __restrict__ W_hh1,  // (256,64)
              const float* __restrict__ b_ih1,
              const float* __restrict__ b_hh1,
              const float* __restrict__ head_W, // (2,64)
              const float* __restrict__ head_b, // (2)
              float* __restrict__ out)          // (32,48,512,2)
{
    extern __shared__ float sm[];
    float4* Wt0q = (float4*)(sm + OFF_WT0);
    float4* Wt1q = (float4*)(sm + OFF_WT1);   // [0..63]=W_ih1, [64..127]=W_hh1
    float* h0T = sm + OFF_H0;
    float* h1T = sm + OFF_H1;
    float* xsT = sm + OFF_XS;                 // two [5][HP] buffers
    float* hw  = sm + OFF_HW;
    float* hb  = sm + OFF_HB;

    const int tid = threadIdx.x;
    const int u = tid & 63;
    const int sg = tid >> 6;
    const int sbase = sg * GRP;               // even -> 8B-aligned pairs
    const int gbase = blockIdx.x * SEQ;

    const ull ONE2  = pk2(1.f, 1.f);
    const ull NTWO2 = pk2(-2.f, -2.f);
    const ull NL2E2 = pk2(-1.4426950408889634f, -1.4426950408889634f);
    const ull TL2E2 = pk2(2.8853900817779268f, 2.8853900817779268f);

    // ---- weights -> smem as per-unit gate quads ----
    for (int e = tid; e < 64 * 64; e += TPB) {
        int j = e >> 6, uu = e & 63;
        Wt0q[j * 64 + uu] = make_float4(W_hh0[uu * 64 + j],
                                        W_hh0[(64 + uu) * 64 + j],
                                        W_hh0[(128 + uu) * 64 + j],
                                        W_hh0[(192 + uu) * 64 + j]);
    }
    for (int e = tid; e < 128 * 64; e += TPB) {
        int j = e >> 6, uu = e & 63;
        const float* src = (j < 64) ? (W_ih1 + j) : (W_hh1 + (j - 64));
        Wt1q[j * 64 + uu] = make_float4(src[uu * 64],
                                        src[(64 + uu) * 64],
                                        src[(128 + uu) * 64],
                                        src[(192 + uu) * 64]);
    }
    for (int e = tid; e < 64 * HP; e += TPB) { h0T[e] = 0.f; h1T[e] = 0.f; }
    if (tid < 128) hw[tid] = head_W[tid];
    if (tid < 2)   hb[tid] = head_b[tid];

    // ---- fold rank-1 embedding into per-gate scalar coefficients ----
    float v1r[4], v2r[4], wcr[4][4], b1r[4];
#pragma unroll
    for (int g = 0; g < 4; g++) {
        int r = g * 64 + u;
        const float* wr = W_ih0 + r * 36;
        float a = 0.f, bb = 0.f;
#pragma unroll
        for (int e = 0; e < 32; e++) {
            a  = fmaf(wr[e], emb_W[e], a);
            bb = fmaf(wr[e], emb_b[e], bb);
        }
        v1r[g] = a;
        v2r[g] = bb + b_ih0[r] + b_hh0[r];
#pragma unroll
        for (int k = 0; k < 4; k++) wcr[g][k] = wr[32 + k];
        b1r[g] = b_ih1[r] + b_hh1[r];
    }

    ull c0p[NPAIR], c1p[NPAIR];
#pragma unroll
    for (int i = 0; i < NPAIR; i++) { c0p[i] = 0ull; c1p[i] = 0ull; }

    const bool duty = (u < GRP);
    const int mys = sbase + (u < GRP ? u : 0);
    int mygs = gbase + mys; if (mygs > NSEQ_TOT - 1) mygs = NSEQ_TOT - 1;
    const int myb = mygs >> 9, myn = mygs & 511;

    const int hb0 = u * HP + sbase;   // this thread's h row base (both layers)

    // ---- prologue: stage x(0) transposed into buf0; prefetch x(1) ----
    float xr0, xr1, xr2, xr3, xr4;
    if (duty) {
        float a0, a1, a2, a3, a4;
        ldx(hist, fut, myb, myn, 0, a0, a1, a2, a3, a4);
        float* xp = xsT + mys;        // column mys of buf0
        xp[0] = a0; xp[HP] = a1; xp[2 * HP] = a2; xp[3 * HP] = a3; xp[4 * HP] = a4;
        ldx(hist, fut, myb, myn, 1, xr0, xr1, xr2, xr3, xr4);
    }
    __syncthreads();   // weights, zero h, x(0) visible

    // acc0(0) = v2 + x(0)-part (h0 is zero -> matvec contributes nothing)
    ull acc0[4][NPAIR];
    {
        ull v2d[4];
#pragma unroll
        for (int g = 0; g < 4; g++) v2d[g] = pk2(v2r[g], v2r[g]);
#pragma unroll
        for (int p = 0; p < NPAIR; p++)
#pragma unroll
            for (int g = 0; g < 4; g++) acc0[g][p] = v2d[g];
        xpart(acc0, xsT + sbase, v1r, wcr);
    }

    for (int t = 0; t < NSTEP; t++) {
        const bool notlast = (t + 1 < NSTEP);

        // ---- phase 1: accB = b1 + W_hh1 @ h1_old, interleaved with packed
        //      U0(t) cell updates; h0(t) stores inlined (h0T free post-bar2).
        ull accB[4][NPAIR];
        {
            ull b1d[4];
#pragma unroll
            for (int g = 0; g < 4; g++) b1d[g] = pk2(b1r[g], b1r[g]);
#pragma unroll
            for (int p = 0; p < NPAIR; p++)
#pragma unroll
                for (int g = 0; g < 4; g++) accB[g][p] = b1d[g];
        }
        {
            const float4* Wq = Wt1q + 64 * 64;   // W_hh1 quads
            const float* H = h1T + sbase;
#pragma unroll
            for (int j = 0; j < 64; j++) {
                float4 w = Wq[j * 64 + u];
                ull W0 = pk2(w.x, w.x), W1 = pk2(w.y, w.y);
                ull W2 = pk2(w.z, w.z), W3 = pk2(w.w, w.w);
                const ull* hr = (const ull*)(H + j * HP);
#pragma unroll
                for (int p = 0; p < NPAIR; p++) {
                    ull h = hr[p];
                    accB[0][p] = fma2(W0, h, accB[0][p]);
                    accB[1][p] = fma2(W1, h, accB[1][p]);
                    accB[2][p] = fma2(W2, h, accB[2][p]);
                    accB[3][p] = fma2(W3, h, accB[3][p]);
                }
                if ((j & 7) == 1) {               // j=1,9,..,49 -> p=0..6
                    const int p = j >> 3;
                    if (p < NPAIR) CELL2(acc0, c0p, p, h0T + hb0 + 2 * p);
                }
            }
        }

        // ---- phase 2: stage x(t+1) transposed; bar1 ----
        if (duty && notlast) {
            float* xp = xsT + ((t + 1) & 1) * XSBUF + mys;
            xp[0] = xr0; xp[HP] = xr1; xp[2 * HP] = xr2;
            xp[3 * HP] = xr3; xp[4 * HP] = xr4;
        }
        __syncthreads();   // bar1: h0(t), x(t+1) visible; h1_old reads done

        // prefetch x(t+2) (latency hidden under phases 3-4)
        if (duty && t + 2 < NSTEP)
            ldx(hist, fut, myb, myn, t + 2, xr0, xr1, xr2, xr3, xr4);

        // ---- phase 3: accB += W_ih1 @ h0(t) ----
        mv64(accB, Wt1q, h0T + sbase, u);

        // ---- phase 4: U1(t) interleaved with acc0(t+1) matvec; inline h1
        //      stores; then packed x(t+1)-projection (accB dead by then).
        if (notlast) {
            {
                ull v2d[4];
#pragma unroll
                for (int g = 0; g < 4; g++) v2d[g] = pk2(v2r[g], v2r[g]);
#pragma unroll
                for (int p = 0; p < NPAIR; p++)
#pragma unroll
                    for (int g = 0; g < 4; g++) acc0[g][p] = v2d[g];
            }
            const float* H0 = h0T + sbase;
#pragma unroll
            for (int j = 0; j < 64; j++) {
                float4 w = Wt0q[j * 64 + u];
                ull W0 = pk2(w.x, w.x), W1 = pk2(w.y, w.y);
                ull W2 = pk2(w.z, w.z), W3 = pk2(w.w, w.w);
                const ull* hr = (const ull*)(H0 + j * HP);
#pragma unroll
                for (int p = 0; p < NPAIR; p++) {
                    ull h = hr[p];
                    acc0[0][p] = fma2(W0, h, acc0[0][p]);
                    acc0[1][p] = fma2(W1, h, acc0[1][p]);
                    acc0[2][p] = fma2(W2, h, acc0[2][p]);
                    acc0[3][p] = fma2(W3, h, acc0[3][p]);
                }
                if ((j & 7) == 1) {
                    const int p = j >> 3;
                    if (p < NPAIR) CELL2(accB, c1p, p, h1T + hb0 + 2 * p);
                }
            }
            xpart(acc0, xsT + ((t + 1) & 1) * XSBUF + sbase, v1r, wcr);
        } else {
#pragma unroll
            for (int p = 0; p < NPAIR; p++)
                CELL2(accB, c1p, p, h1T + hb0 + 2 * p);
        }
        __syncthreads();   // bar2: h1(t) visible

        // ---- head (last 48 steps; duty threads, 1 seq each) ----
        if (t >= 335 && duty) {
            float p0 = hb[0], p1 = hb[1];
#pragma unroll 8
            for (int j = 0; j < 64; j++) {
                float v = fmaxf(h1T[j * HP + mys], 0.f);
                p0 = fmaf(v, hw[j], p0);
                p1 = fmaf(v, hw[64 + j], p1);
            }
            float sp = (p1 > 15.f) ? p1 : log1pf(__expf(p1));
            ((float2*)out)[((size_t)myb * 48 + (t - 335)) * 512 + myn] =
                make_float2(p0, sp);
        }
        // h1T next overwritten in phase 4 of t+1 (after bar1) -> head safe
    }
}

extern "C" void kernel_launch(void* const* d_in, const int* in_sizes, int n_in,
                              void* d_out, int out_size) {
    (void)in_sizes; (void)n_in; (void)out_size;
    const float* hist   = (const float*)d_in[0];
    const float* fut    = (const float*)d_in[1];
    const float* emb_W  = (const float*)d_in[2];
    const float* emb_b  = (const float*)d_in[3];
    const float* W_ih0  = (const float*)d_in[4];
    const float* W_hh0  = (const float*)d_in[5];
    const float* b_ih0  = (const float*)d_in[6];
    const float* b_hh0  = (const float*)d_in[7];
    const float* W_ih1  = (const float*)d_in[8];
    const float* W_hh1  = (const float*)d_in[9];
    const float* b_ih1  = (const float*)d_in[10];
    const float* b_hh1  = (const float*)d_in[11];
    const float* head_W = (const float*)d_in[12];
    const float* head_b = (const float*)d_in[13];
    float* out = (float*)d_out;

    cudaFuncSetAttribute(deepar_kernel,
                         cudaFuncAttributeMaxDynamicSharedMemorySize, SM_BYTES);

    deepar_kernel<<<NCTA, TPB, SM_BYTES>>>(
        hist, fut, emb_W, emb_b,
        W_ih0, W_hh0, b_ih0, b_hh0,
        W_ih1, W_hh1, b_ih1, b_hh1,
        head_W, head_b, out);
}

// round 10
// speedup vs baseline: 1.1012x; 1.0998x over previous
#include <cuda_runtime.h>

// DeepAR forward: 2-layer LSTM (H=64), T=383 steps, 16384 independent seqs.
// Persistent: 296 CTAs (2 full waves on 148 SMs) x 256 threads, 56 seqs/CTA.
// Structure = R6 (best known: software-pipelined step, MUFU interleaved with
// independent fma.rn.f32x2 matvec rows, 2 barriers/step).
// R9 single change: activations use HW MUFU.TANH (tanh.approx.f32):
//   tanh(x)    = tanh.approx(x)                      (1 MUFU vs 2 MUFU + 4 ops)
//   sigmoid(x) = 0.5*tanh.approx(0.5x) + 0.5         (1 MUFU + 2 FMA vs 2+3)
// ~450 fewer ops/thread/step; MUFU count halved; chains 3x shorter.
// Precision experiment: tanh.approx abs err ~6e-4/activation; expected final
// rel_err ~1e-4 (gate 1e-3).

#define TPB 256
#define SEQ 56          // sequences per CTA (4 groups x 14)
#define GRP 14
#define NPAIR 7         // seq pairs per thread
#define NCTA 296        // 2 x 148 -> two full waves
#define NSTEP 383
#define NSEQ_TOT 16384
#define HP 58           // h-state row pitch (even -> 8B-aligned pairs)

// shared layout (floats)
#define OFF_WT0 0               // [64][64] float4 quads   16384
#define OFF_WT1 16384           // [128][64] float4 quads  32768
#define OFF_H0  49152           // [64][HP]                 3712
#define OFF_H1  52864           // [64][HP]                 3712
#define OFF_XS  56576           // 2 x [64][5] double-buf    640
#define OFF_HW  57216           // head_W (2x64)             128
#define OFF_HB  57344           // head_b                      2
#define SM_FLOATS 57346
#define SM_BYTES (SM_FLOATS * 4)

typedef unsigned long long ull;

static __device__ __forceinline__ ull pk2(float a, float b) {
    ull r; asm("mov.b64 %0, {%1, %2};" : "=l"(r) : "f"(a), "f"(b)); return r;
}
static __device__ __forceinline__ void upk2(ull v, float& a, float& b) {
    asm("mov.b64 {%0, %1}, %2;" : "=f"(a), "=f"(b) : "l"(v));
}
static __device__ __forceinline__ ull fma2(ull a, ull b, ull c) {
    ull d; asm("fma.rn.f32x2 %0, %1, %2, %3;" : "=l"(d) : "l"(a), "l"(b), "l"(c)); return d;
}

// HW tanh (MUFU.TANH, sm_75+; single op)
static __device__ __forceinline__ float tanh_(float x) {
    float r; asm("tanh.approx.f32 %0, %1;" : "=f"(r) : "f"(x)); return r;
}
// sigmoid via tanh identity: 0.5*tanh(0.5x) + 0.5
static __device__ __forceinline__ float sigm_(float x) {
    return fmaf(0.5f, tanh_(0.5f * x), 0.5f);
}

// LSTM cell update for one sequence pair.
#define CELL_UPDATE(accA, cv, hnew, p) do {                                   \
    float i0_, i1_, f0_, f1_, g0_, g1_, o0_, o1_;                             \
    upk2(accA[0][p], i0_, i1_);                                               \
    upk2(accA[1][p], f0_, f1_);                                               \
    upk2(accA[2][p], g0_, g1_);                                               \
    upk2(accA[3][p], o0_, o1_);                                               \
    float ca_ = sigm_(f0_) * cv[2*(p)]     + sigm_(i0_) * tanh_(g0_);         \
    float cb_ = sigm_(f1_) * cv[2*(p)+1]   + sigm_(i1_) * tanh_(g1_);         \
    cv[2*(p)] = ca_; cv[2*(p)+1] = cb_;                                       \
    hnew[p] = pk2(sigm_(o0_) * tanh_(ca_), sigm_(o1_) * tanh_(cb_));          \
} while (0)

// plain matvec: acc[g][p] += Wq[j][u].{xyzw} * h[j][pair p]
static __device__ __forceinline__ void mv64(ull (&acc)[4][NPAIR],
                                            const float4* __restrict__ Wq,
                                            const float* __restrict__ H,
                                            int u) {
#pragma unroll 8
    for (int j = 0; j < 64; j++) {
        float4 w = Wq[j * 64 + u];
        ull W0 = pk2(w.x, w.x), W1 = pk2(w.y, w.y);
        ull W2 = pk2(w.z, w.z), W3 = pk2(w.w, w.w);
        const ull* hr = (const ull*)(H + j * HP);
#pragma unroll
        for (int p = 0; p < NPAIR; p++) {
            ull h = hr[p];
            acc[0][p] = fma2(W0, h, acc[0][p]);
            acc[1][p] = fma2(W1, h, acc[1][p]);
            acc[2][p] = fma2(W2, h, acc[2][p]);
            acc[3][p] = fma2(W3, h, acc[3][p]);
        }
    }
}

// x-fetch: prev target at time t, covariates at time t+1 (t in [0,382])
static __device__ __forceinline__ void ldx(const float* __restrict__ hist,
                                           const float* __restrict__ fut,
                                           int myb, int myn, int t,
                                           float& x0, float& x1, float& x2,
                                           float& x3, float& x4) {
    const float* s1 = (t < 336)
        ? hist + (((size_t)myb * 336 + t) * 512 + myn) * 5
        : fut  + (((size_t)myb * 48 + (t - 336)) * 512 + myn) * 5;
    int tc = t + 1;
    const float* s2 = (tc < 336)
        ? hist + (((size_t)myb * 336 + tc) * 512 + myn) * 5
        : fut  + (((size_t)myb * 48 + (tc - 336)) * 512 + myn) * 5;
    x0 = s1[0];
    x1 = s2[1]; x2 = s2[2]; x3 = s2[3]; x4 = s2[4];
}

extern "C" __global__ void __launch_bounds__(TPB, 1)
deepar_kernel(const float* __restrict__ hist,   // (32,336,512,5)
              const float* __restrict__ fut,    // (32, 48,512,5)
              const float* __restrict__ emb_W,  // (32,1)
              const float* __restrict__ emb_b,  // (32)
              const float* __restrict__ W_ih0,  // (256,36)
              const float* __restrict__ W_hh0,  // (256,64)
              const float* __restrict__ b_ih0,
              const float* __restrict__ b_hh0,
              const float* __restrict__ W_ih1,  // (256,64)
              const float* __restrict__ W_hh1,  // (256,64)
              const float* __restrict__ b_ih1,
              const float* __restrict__ b_hh1,
              const float* __restrict__ head_W, // (2,64)
              const float* __restrict__ head_b, // (2)
              float* __restrict__ out)          // (32,48,512,2)
{
    extern __shared__ float sm[];
    float4* Wt0q = (float4*)(sm + OFF_WT0);
    float4* Wt1q = (float4*)(sm + OFF_WT1);   // [0..63]=W_ih1, [64..127]=W_hh1
    float* h0T = sm + OFF_H0;
    float* h1T = sm + OFF_H1;
    float* xs  = sm + OFF_XS;                 // two buffers of 320 floats
    float* hw  = sm + OFF_HW;
    float* hb  = sm + OFF_HB;

    const int tid = threadIdx.x;
    const int u = tid & 63;
    const int sg = tid >> 6;
    const int sbase = sg * GRP;               // even -> 8B-aligned pairs
    const int gbase = blockIdx.x * SEQ;

    // ---- weights -> smem as per-unit gate quads ----
    for (int e = tid; e < 64 * 64; e += TPB) {
        int j = e >> 6, uu = e & 63;
        Wt0q[j * 64 + uu] = make_float4(W_hh0[uu * 64 + j],
                                        W_hh0[(64 + uu) * 64 + j],
                                        W_hh0[(128 + uu) * 64 + j],
                                        W_hh0[(192 + uu) * 64 + j]);
    }
    for (int e = tid; e < 128 * 64; e += TPB) {
        int j = e >> 6, uu = e & 63;
        const float* src = (j < 64) ? (W_ih1 + j) : (W_hh1 + (j - 64));
        Wt1q[j * 64 + uu] = make_float4(src[uu * 64],
                                        src[(64 + uu) * 64],
                                        src[(128 + uu) * 64],
                                        src[(192 + uu) * 64]);
    }
    for (int e = tid; e < 64 * HP; e += TPB) { h0T[e] = 0.f; h1T[e] = 0.f; }
    if (tid < 128) hw[tid] = head_W[tid];
    if (tid < 2)   hb[tid] = head_b[tid];

    // ---- fold rank-1 embedding into per-gate scalar coefficients ----
    float v1r[4], v2r[4], wcr[4][4], b1r[4];
#pragma unroll
    for (int g = 0; g < 4; g++) {
        int r = g * 64 + u;
        const float* wr = W_ih0 + r * 36;
        float a = 0.f, bb = 0.f;
#pragma unroll
        for (int e = 0; e < 32; e++) {
            a  = fmaf(wr[e], emb_W[e], a);
            bb = fmaf(wr[e], emb_b[e], bb);
        }
        v1r[g] = a;
        v2r[g] = bb + b_ih0[r] + b_hh0[r];
#pragma unroll
        for (int k = 0; k < 4; k++) wcr[g][k] = wr[32 + k];
        b1r[g] = b_ih1[r] + b_hh1[r];
    }

    float c0v[2 * NPAIR], c1v[2 * NPAIR];
#pragma unroll
    for (int i = 0; i < 2 * NPAIR; i++) { c0v[i] = 0.f; c1v[i] = 0.f; }

    const bool duty = (u < GRP);
    const int mys = sbase + (u < GRP ? u : 0);
    int mygs = gbase + mys; if (mygs > NSEQ_TOT - 1) mygs = NSEQ_TOT - 1;
    const int myb = mygs >> 9, myn = mygs & 511;

    // ---- prologue: stage x(0), prefetch x(1) ----
    float xr0, xr1, xr2, xr3, xr4;
    if (duty) {
        float a0, a1, a2, a3, a4;
        ldx(hist, fut, myb, myn, 0, a0, a1, a2, a3, a4);
        float* xp = xs + mys * 5;
        xp[0] = a0; xp[1] = a1; xp[2] = a2; xp[3] = a3; xp[4] = a4;
        ldx(hist, fut, myb, myn, 1, xr0, xr1, xr2, xr3, xr4);
    }
    __syncthreads();   // weights, zero h, x(0) visible

    // acc0(0) = pre0(x(0)) + W_hh0 @ h0(=0)
    ull acc0[4][NPAIR];
#pragma unroll
    for (int p = 0; p < NPAIR; p++) {
        const float* xa = xs + (sbase + 2 * p) * 5;
        const float* xb = xa + 5;
#pragma unroll
        for (int g = 0; g < 4; g++) {
            float lo = v2r[g], hi = v2r[g];
            lo = fmaf(xa[0], v1r[g], lo);
            hi = fmaf(xb[0], v1r[g], hi);
#pragma unroll
            for (int k = 0; k < 4; k++) {
                lo = fmaf(xa[1 + k], wcr[g][k], lo);
                hi = fmaf(xb[1 + k], wcr[g][k], hi);
            }
            acc0[g][p] = pk2(lo, hi);
        }
    }
    mv64(acc0, Wt0q, h0T + sbase, u);
    __syncthreads();   // all pre-loop h0 reads done (S0(0) WAR guard)

    for (int t = 0; t < NSTEP; t++) {
        const bool notlast = (t + 1 < NSTEP);

        // ---- phase 1: U0(t) [MUFU] interleaved with accB = W_hh1 @ h1_old
        ull accB[4][NPAIR];
#pragma unroll
        for (int p = 0; p < NPAIR; p++) {
#pragma unroll
            for (int g = 0; g < 4; g++) accB[g][p] = pk2(b1r[g], b1r[g]);
        }
        ull h0new[NPAIR];
        {
            const float4* Wq = Wt1q + 64 * 64;   // W_hh1 quads
            const float* H = h1T + sbase;
#pragma unroll
            for (int j = 0; j < 64; j++) {
                float4 w = Wq[j * 64 + u];
                ull W0 = pk2(w.x, w.x), W1 = pk2(w.y, w.y);
                ull W2 = pk2(w.z, w.z), W3 = pk2(w.w, w.w);
                const ull* hr = (const ull*)(H + j * HP);
#pragma unroll
                for (int p = 0; p < NPAIR; p++) {
                    ull h = hr[p];
                    accB[0][p] = fma2(W0, h, accB[0][p]);
                    accB[1][p] = fma2(W1, h, accB[1][p]);
                    accB[2][p] = fma2(W2, h, accB[2][p]);
                    accB[3][p] = fma2(W3, h, accB[3][p]);
                }
                if ((j & 7) == 1) {               // 8 slots, 7 pairs
                    const int p = j >> 3;
                    if (p < NPAIR) CELL_UPDATE(acc0, c0v, h0new, p);
                }
            }
        }

        // ---- phase 2: store h0(t); stage x(t+1) ----
        {
            const int hbase = u * HP + sbase;
#pragma unroll
            for (int p = 0; p < NPAIR; p++)
                *(ull*)(h0T + hbase + 2 * p) = h0new[p];
        }
        if (duty && notlast) {
            float* xp = xs + ((t + 1) & 1) * 320 + mys * 5;
            xp[0] = xr0; xp[1] = xr1; xp[2] = xr2; xp[3] = xr3; xp[4] = xr4;
        }
        __syncthreads();   // bar1: h0(t), x(t+1) visible; h1_old reads done

        // prefetch x(t+2) (latency hidden under phases 3-4)
        if (duty && t + 2 < NSTEP)
            ldx(hist, fut, myb, myn, t + 2, xr0, xr1, xr2, xr3, xr4);

        // ---- phase 3: acc1 = accB + W_ih1 @ h0(t) ----
        mv64(accB, Wt1q, h0T + sbase, u);

        // ---- phase 4: U1(t) [MUFU] interleaved with acc0(t+1) matvec ----
        ull h1new[NPAIR];
        if (notlast) {
            const float* cur = xs + ((t + 1) & 1) * 320;
#pragma unroll
            for (int p = 0; p < NPAIR; p++) {
                const float* xa = cur + (sbase + 2 * p) * 5;
                const float* xb = xa + 5;
#pragma unroll
                for (int g = 0; g < 4; g++) {
                    float lo = v2r[g], hi = v2r[g];
                    lo = fmaf(xa[0], v1r[g], lo);
                    hi = fmaf(xb[0], v1r[g], hi);
#pragma unroll
                    for (int k = 0; k < 4; k++) {
                        lo = fmaf(xa[1 + k], wcr[g][k], lo);
                        hi = fmaf(xb[1 + k], wcr[g][k], hi);
                    }
                    acc0[g][p] = pk2(lo, hi);
                }
            }
            const float* H0 = h0T + sbase;
#pragma unroll
            for (int j = 0; j < 64; j++) {
                float4 w = Wt0q[j * 64 + u];
                ull W0 = pk2(w.x, w.x), W1 = pk2(w.y, w.y);
                ull W2 = pk2(w.z, w.z), W3 = pk2(w.w, w.w);
                const ull* hr = (const ull*)(H0 + j * HP);
#pragma unroll
                for (int p = 0; p < NPAIR; p++) {
                    ull h = hr[p];
                    acc0[0][p] = fma2(W0, h, acc0[0][p]);
                    acc0[1][p] = fma2(W1, h, acc0[1][p]);
                    acc0[2][p] = fma2(W2, h, acc0[2][p]);
                    acc0[3][p] = fma2(W3, h, acc0[3][p]);
                }
                if ((j & 7) == 1) {
                    const int p = j >> 3;
                    if (p < NPAIR) CELL_UPDATE(accB, c1v, h1new, p);
                }
            }
        } else {
#pragma unroll
            for (int p = 0; p < NPAIR; p++) CELL_UPDATE(accB, c1v, h1new, p);
        }

        // ---- phase 5: store h1(t) ----
        {
            const int hbase = u * HP + sbase;
#pragma unroll
            for (int p = 0; p < NPAIR; p++)
                *(ull*)(h1T + hbase + 2 * p) = h1new[p];
        }
        __syncthreads();   // bar2: h1(t) visible

        // ---- head (last 48 steps; exact math, negligible cost) ----
        if (t >= 335 && duty) {
            float p0 = hb[0], p1 = hb[1];
#pragma unroll 8
            for (int j = 0; j < 64; j++) {
                float v = fmaxf(h1T[j * HP + mys], 0.f);
                p0 = fmaf(v, hw[j], p0);
                p1 = fmaf(v, hw[64 + j], p1);
            }
            float sp = (p1 > 15.f) ? p1 : log1pf(__expf(p1));
            ((float2*)out)[((size_t)myb * 48 + (t - 335)) * 512 + myn] =
                make_float2(p0, sp);
        }
        // h1T next overwritten after bar1 of step t+1 -> head read safe
    }
}

extern "C" void kernel_launch(void* const* d_in, const int* in_sizes, int n_in,
                              void* d_out, int out_size) {
    (void)in_sizes; (void)n_in; (void)out_size;
    const float* hist   = (const float*)d_in[0];
    const float* fut    = (const float*)d_in[1];
    const float* emb_W  = (const float*)d_in[2];
    const float* emb_b  = (const float*)d_in[3];
    const float* W_ih0  = (const float*)d_in[4];
    const float* W_hh0  = (const float*)d_in[5];
    const float* b_ih0  = (const float*)d_in[6];
    const float* b_hh0  = (const float*)d_in[7];
    const float* W_ih1  = (const float*)d_in[8];
    const float* W_hh1  = (const float*)d_in[9];
    const float* b_ih1  = (const float*)d_in[10];
    const float* b_hh1  = (const float*)d_in[11];
    const float* head_W = (const float*)d_in[12];
    const float* head_b = (const float*)d_in[13];
    float* out = (float*)d_out;

    cudaFuncSetAttribute(deepar_kernel,
                         cudaFuncAttributeMaxDynamicSharedMemorySize, SM_BYTES);

    deepar_kernel<<<NCTA, TPB, SM_BYTES>>>(
        hist, fut, emb_W, emb_b,
        W_ih0, W_hh0, b_ih0, b_hh0,
        W_ih1, W_hh1, b_ih1, b_hh1,
        head_W, head_b, out);
}

// round 11
// speedup vs baseline: 1.1039x; 1.0024x over previous
#include <cuda_runtime.h>

// DeepAR forward: 2-layer LSTM (H=64), T=383 steps, 16384 independent seqs.
// Persistent: 296 CTAs (2 full waves on 148 SMs) x 256 threads, 56 seqs/CTA.
// Structure = R6 (best known: software-pipelined step, MUFU interleaved with
// independent fma.rn.f32x2 matvec rows, 2 barriers/step).
// R9 single change: activations use HW MUFU.TANH (tanh.approx.f32):
//   tanh(x)    = tanh.approx(x)                      (1 MUFU vs 2 MUFU + 4 ops)
//   sigmoid(x) = 0.5*tanh.approx(0.5x) + 0.5         (1 MUFU + 2 FMA vs 2+3)
// ~450 fewer ops/thread/step; MUFU count halved; chains 3x shorter.
// Precision experiment: tanh.approx abs err ~6e-4/activation; expected final
// rel_err ~1e-4 (gate 1e-3).

#define TPB 256
#define SEQ 56          // sequences per CTA (4 groups x 14)
#define GRP 14
#define NPAIR 7         // seq pairs per thread
#define NCTA 296        // 2 x 148 -> two full waves
#define NSTEP 383
#define NSEQ_TOT 16384
#define HP 58           // h-state row pitch (even -> 8B-aligned pairs)

// shared layout (floats)
#define OFF_WT0 0               // [64][64] float4 quads   16384
#define OFF_WT1 16384           // [128][64] float4 quads  32768
#define OFF_H0  49152           // [64][HP]                 3712
#define OFF_H1  52864           // [64][HP]                 3712
#define OFF_XS  56576           // 2 x [64][5] double-buf    640
#define OFF_HW  57216           // head_W (2x64)             128
#define OFF_HB  57344           // head_b                      2
#define SM_FLOATS 57346
#define SM_BYTES (SM_FLOATS * 4)

typedef unsigned long long ull;

static __device__ __forceinline__ ull pk2(float a, float b) {
    ull r; asm("mov.b64 %0, {%1, %2};" : "=l"(r) : "f"(a), "f"(b)); return r;
}
static __device__ __forceinline__ void upk2(ull v, float& a, float& b) {
    asm("mov.b64 {%0, %1}, %2;" : "=f"(a), "=f"(b) : "l"(v));
}
static __device__ __forceinline__ ull fma2(ull a, ull b, ull c) {
    ull d; asm("fma.rn.f32x2 %0, %1, %2, %3;" : "=l"(d) : "l"(a), "l"(b), "l"(c)); return d;
}

// HW tanh (MUFU.TANH, sm_75+; single op)
static __device__ __forceinline__ float tanh_(float x) {
    float r; asm("tanh.approx.f32 %0, %1;" : "=f"(r) : "f"(x)); return r;
}
// sigmoid via tanh identity: 0.5*tanh(0.5x) + 0.5
static __device__ __forceinline__ float sigm_(float x) {
    return fmaf(0.5f, tanh_(0.5f * x), 0.5f);
}

// LSTM cell update for one sequence pair.
#define CELL_UPDATE(accA, cv, hnew, p) do {                                   \
    float i0_, i1_, f0_, f1_, g0_, g1_, o0_, o1_;                             \
    upk2(accA[0][p], i0_, i1_);                                               \
    upk2(accA[1][p], f0_, f1_);                                               \
    upk2(accA[2][p], g0_, g1_);                                               \
    upk2(accA[3][p], o0_, o1_);                                               \
    float ca_ = sigm_(f0_) * cv[2*(p)]     + sigm_(i0_) * tanh_(g0_);         \
    float cb_ = sigm_(f1_) * cv[2*(p)+1]   + sigm_(i1_) * tanh_(g1_);         \
    cv[2*(p)] = ca_; cv[2*(p)+1] = cb_;                                       \
    hnew[p] = pk2(sigm_(o0_) * tanh_(ca_), sigm_(o1_) * tanh_(cb_));          \
} while (0)

// plain matvec: acc[g][p] += Wq[j][u].{xyzw} * h[j][pair p]
static __device__ __forceinline__ void mv64(ull (&acc)[4][NPAIR],
                                            const float4* __restrict__ Wq,
                                            const float* __restrict__ H,
                                            int u) {
#pragma unroll 8
    for (int j = 0; j < 64; j++) {
        float4 w = Wq[j * 64 + u];
        ull W0 = pk2(w.x, w.x), W1 = pk2(w.y, w.y);
        ull W2 = pk2(w.z, w.z), W3 = pk2(w.w, w.w);
        const ull* hr = (const ull*)(H + j * HP);
#pragma unroll
        for (int p = 0; p < NPAIR; p++) {
            ull h = hr[p];
            acc[0][p] = fma2(W0, h, acc[0][p]);
            acc[1][p] = fma2(W1, h, acc[1][p]);
            acc[2][p] = fma2(W2, h, acc[2][p]);
            acc[3][p] = fma2(W3, h, acc[3][p]);
        }
    }
}

// x-fetch: prev target at time t, covariates at time t+1 (t in [0,382])
static __device__ __forceinline__ void ldx(const float* __restrict__ hist,
                                           const float* __restrict__ fut,
                                           int myb, int myn, int t,
                                           float& x0, float& x1, float& x2,
                                           float& x3, float& x4) {
    const float* s1 = (t < 336)
        ? hist + (((size_t)myb * 336 + t) * 512 + myn) * 5
        : fut  + (((size_t)myb * 48 + (t - 336)) * 512 + myn) * 5;
    int tc = t + 1;
    const float* s2 = (tc < 336)
        ? hist + (((size_t)myb * 336 + tc) * 512 + myn) * 5
        : fut  + (((size_t)myb * 48 + (tc - 336)) * 512 + myn) * 5;
    x0 = s1[0];
    x1 = s2[1]; x2 = s2[2]; x3 = s2[3]; x4 = s2[4];
}

extern "C" __global__ void __launch_bounds__(TPB, 1)
deepar_kernel(const float* __restrict__ hist,   // (32,336,512,5)
              const float* __restrict__ fut,    // (32, 48,512,5)
              const float* __restrict__ emb_W,  // (32,1)
              const float* __restrict__ emb_b,  // (32)
              const float* __restrict__ W_ih0,  // (256,36)
              const float* __restrict__ W_hh0,  // (256,64)
              const float* __restrict__ b_ih0,
              const float* __restrict__ b_hh0,
              const float* __restrict__ W_ih1,  // (256,64)
              const float* __restrict__ W_hh1,  // (256,64)
              const float* __restrict__ b_ih1,
              const float* __restrict__ b_hh1,
              const float* __restrict__ head_W, // (2,64)
              const float* __restrict__ head_b, // (2)
              float* __restrict__ out)          // (32,48,512,2)
{
    extern __shared__ float sm[];
    float4* Wt0q = (float4*)(sm + OFF_WT0);
    float4* Wt1q = (float4*)(sm + OFF_WT1);   // [0..63]=W_ih1, [64..127]=W_hh1
    float* h0T = sm + OFF_H0;
    float* h1T = sm + OFF_H1;
    float* xs  = sm + OFF_XS;                 // two buffers of 320 floats
    float* hw  = sm + OFF_HW;
    float* hb  = sm + OFF_HB;

    const int tid = threadIdx.x;
    const int u = tid & 63;
    const int sg = tid >> 6;
    const int sbase = sg * GRP;               // even -> 8B-aligned pairs
    const int gbase = blockIdx.x * SEQ;

    // ---- weights -> smem as per-unit gate quads ----
    for (int e = tid; e < 64 * 64; e += TPB) {
        int j = e >> 6, uu = e & 63;
        Wt0q[j * 64 + uu] = make_float4(W_hh0[uu * 64 + j],
                                        W_hh0[(64 + uu) * 64 + j],
                                        W_hh0[(128 + uu) * 64 + j],
                                        W_hh0[(192 + uu) * 64 + j]);
    }
    for (int e = tid; e < 128 * 64; e += TPB) {
        int j = e >> 6, uu = e & 63;
        const float* src = (j < 64) ? (W_ih1 + j) : (W_hh1 + (j - 64));
        Wt1q[j * 64 + uu] = make_float4(src[uu * 64],
                                        src[(64 + uu) * 64],
                                        src[(128 + uu) * 64],
                                        src[(192 + uu) * 64]);
    }
    for (int e = tid; e < 64 * HP; e += TPB) { h0T[e] = 0.f; h1T[e] = 0.f; }
    if (tid < 128) hw[tid] = head_W[tid];
    if (tid < 2)   hb[tid] = head_b[tid];

    // ---- fold rank-1 embedding into per-gate scalar coefficients ----
    float v1r[4], v2r[4], wcr[4][4], b1r[4];
#pragma unroll
    for (int g = 0; g < 4; g++) {
        int r = g * 64 + u;
        const float* wr = W_ih0 + r * 36;
        float a = 0.f, bb = 0.f;
#pragma unroll
        for (int e = 0; e < 32; e++) {
            a  = fmaf(wr[e], emb_W[e], a);
            bb = fmaf(wr[e], emb_b[e], bb);
        }
        v1r[g] = a;
        v2r[g] = bb + b_ih0[r] + b_hh0[r];
#pragma unroll
        for (int k = 0; k < 4; k++) wcr[g][k] = wr[32 + k];
        b1r[g] = b_ih1[r] + b_hh1[r];
    }

    float c0v[2 * NPAIR], c1v[2 * NPAIR];
#pragma unroll
    for (int i = 0; i < 2 * NPAIR; i++) { c0v[i] = 0.f; c1v[i] = 0.f; }

    const bool duty = (u < GRP);
    const int mys = sbase + (u < GRP ? u : 0);
    int mygs = gbase + mys; if (mygs > NSEQ_TOT - 1) mygs = NSEQ_TOT - 1;
    const int myb = mygs >> 9, myn = mygs & 511;

    // ---- prologue: stage x(0), prefetch x(1) ----
    float xr0, xr1, xr2, xr3, xr4;
    if (duty) {
        float a0, a1, a2, a3, a4;
        ldx(hist, fut, myb, myn, 0, a0, a1, a2, a3, a4);
        float* xp = xs + mys * 5;
        xp[0] = a0; xp[1] = a1; xp[2] = a2; xp[3] = a3; xp[4] = a4;
        ldx(hist, fut, myb, myn, 1, xr0, xr1, xr2, xr3, xr4);
    }
    __syncthreads();   // weights, zero h, x(0) visible

    // acc0(0) = pre0(x(0)) + W_hh0 @ h0(=0)
    ull acc0[4][NPAIR];
#pragma unroll
    for (int p = 0; p < NPAIR; p++) {
        const float* xa = xs + (sbase + 2 * p) * 5;
        const float* xb = xa + 5;
#pragma unroll
        for (int g = 0; g < 4; g++) {
            float lo = v2r[g], hi = v2r[g];
            lo = fmaf(xa[0], v1r[g], lo);
            hi = fmaf(xb[0], v1r[g], hi);
#pragma unroll
            for (int k = 0; k < 4; k++) {
                lo = fmaf(xa[1 + k], wcr[g][k], lo);
                hi = fmaf(xb[1 + k], wcr[g][k], hi);
            }
            acc0[g][p] = pk2(lo, hi);
        }
    }
    mv64(acc0, Wt0q, h0T + sbase, u);
    __syncthreads();   // all pre-loop h0 reads done (S0(0) WAR guard)

    for (int t = 0; t < NSTEP; t++) {
        const bool notlast = (t + 1 < NSTEP);

        // ---- phase 1: U0(t) [MUFU] interleaved with accB = W_hh1 @ h1_old
        ull accB[4][NPAIR];
#pragma unroll
        for (int p = 0; p < NPAIR; p++) {
#pragma unroll
            for (int g = 0; g < 4; g++) accB[g][p] = pk2(b1r[g], b1r[g]);
        }
        ull h0new[NPAIR];
        {
            const float4* Wq = Wt1q + 64 * 64;   // W_hh1 quads
            const float* H = h1T + sbase;
#pragma unroll
            for (int j = 0; j < 64; j++) {
                float4 w = Wq[j * 64 + u];
                ull W0 = pk2(w.x, w.x), W1 = pk2(w.y, w.y);
                ull W2 = pk2(w.z, w.z), W3 = pk2(w.w, w.w);
                const ull* hr = (const ull*)(H + j * HP);
#pragma unroll
                for (int p = 0; p < NPAIR; p++) {
                    ull h = hr[p];
                    accB[0][p] = fma2(W0, h, accB[0][p]);
                    accB[1][p] = fma2(W1, h, accB[1][p]);
                    accB[2][p] = fma2(W2, h, accB[2][p]);
                    accB[3][p] = fma2(W3, h, accB[3][p]);
                }
                if ((j & 7) == 1) {               // 8 slots, 7 pairs
                    const int p = j >> 3;
                    if (p < NPAIR) CELL_UPDATE(acc0, c0v, h0new, p);
                }
            }
        }

        // ---- phase 2: store h0(t); stage x(t+1) ----
        {
            const int hbase = u * HP + sbase;
#pragma unroll
            for (int p = 0; p < NPAIR; p++)
                *(ull*)(h0T + hbase + 2 * p) = h0new[p];
        }
        if (duty && notlast) {
            float* xp = xs + ((t + 1) & 1) * 320 + mys * 5;
            xp[0] = xr0; xp[1] = xr1; xp[2] = xr2; xp[3] = xr3; xp[4] = xr4;
        }
        __syncthreads();   // bar1: h0(t), x(t+1) visible; h1_old reads done

        // prefetch x(t+2) (latency hidden under phases 3-4)
        if (duty && t + 2 < NSTEP)
            ldx(hist, fut, myb, myn, t + 2, xr0, xr1, xr2, xr3, xr4);

        // ---- phase 3: acc1 = accB + W_ih1 @ h0(t) ----
        mv64(accB, Wt1q, h0T + sbase, u);

        // ---- phase 4: U1(t) [MUFU] interleaved with acc0(t+1) matvec ----
        ull h1new[NPAIR];
        if (notlast) {
            const float* cur = xs + ((t + 1) & 1) * 320;
#pragma unroll
            for (int p = 0; p < NPAIR; p++) {
                const float* xa = cur + (sbase + 2 * p) * 5;
                const float* xb = xa + 5;
#pragma unroll
                for (int g = 0; g < 4; g++) {
                    float lo = v2r[g], hi = v2r[g];
                    lo = fmaf(xa[0], v1r[g], lo);
                    hi = fmaf(xb[0], v1r[g], hi);
#pragma unroll
                    for (int k = 0; k < 4; k++) {
                        lo = fmaf(xa[1 + k], wcr[g][k], lo);
                        hi = fmaf(xb[1 + k], wcr[g][k], hi);
                    }
                    acc0[g][p] = pk2(lo, hi);
                }
            }
            const float* H0 = h0T + sbase;
#pragma unroll
            for (int j = 0; j < 64; j++) {
                float4 w = Wt0q[j * 64 + u];
                ull W0 = pk2(w.x, w.x), W1 = pk2(w.y, w.y);
                ull W2 = pk2(w.z, w.z), W3 = pk2(w.w, w.w);
                const ull* hr = (const ull*)(H0 + j * HP);
#pragma unroll
                for (int p = 0; p < NPAIR; p++) {
                    ull h = hr[p];
                    acc0[0][p] = fma2(W0, h, acc0[0][p]);
                    acc0[1][p] = fma2(W1, h, acc0[1][p]);
                    acc0[2][p] = fma2(W2, h, acc0[2][p]);
                    acc0[3][p] = fma2(W3, h, acc0[3][p]);
                }
                if ((j & 7) == 1) {
                    const int p = j >> 3;
                    if (p < NPAIR) CELL_UPDATE(accB, c1v, h1new, p);
                }
            }
        } else {
#pragma unroll
            for (int p = 0; p < NPAIR; p++) CELL_UPDATE(accB, c1v, h1new, p);
        }

        // ---- phase 5: store h1(t) ----
        {
            const int hbase = u * HP + sbase;
#pragma unroll
            for (int p = 0; p < NPAIR; p++)
                *(ull*)(h1T + hbase + 2 * p) = h1new[p];
        }
        __syncthreads();   // bar2: h1(t) visible

        // ---- head (last 48 steps; exact math, negligible cost) ----
        if (t >= 335 && duty) {
            float p0 = hb[0], p1 = hb[1];
#pragma unroll 8
            for (int j = 0; j < 64; j++) {
                float v = fmaxf(h1T[j * HP + mys], 0.f);
                p0 = fmaf(v, hw[j], p0);
                p1 = fmaf(v, hw[64 + j], p1);
            }
            float sp = (p1 > 15.f) ? p1 : log1pf(__expf(p1));
            ((float2*)out)[((size_t)myb * 48 + (t - 335)) * 512 + myn] =
                make_float2(p0, sp);
        }
        // h1T next overwritten after bar1 of step t+1 -> head read safe
    }
}

extern "C" void kernel_launch(void* const* d_in, const int* in_sizes, int n_in,
                              void* d_out, int out_size) {
    (void)in_sizes; (void)n_in; (void)out_size;
    const float* hist   = (const float*)d_in[0];
    const float* fut    = (const float*)d_in[1];
    const float* emb_W  = (const float*)d_in[2];
    const float* emb_b  = (const float*)d_in[3];
    const float* W_ih0  = (const float*)d_in[4];
    const float* W_hh0  = (const float*)d_in[5];
    const float* b_ih0  = (const float*)d_in[6];
    const float* b_hh0  = (const float*)d_in[7];
    const float* W_ih1  = (const float*)d_in[8];
    const float* W_hh1  = (const float*)d_in[9];
    const float* b_ih1  = (const float*)d_in[10];
    const float* b_hh1  = (const float*)d_in[11];
    const float* head_W = (const float*)d_in[12];
    const float* head_b = (const float*)d_in[13];
    float* out = (float*)d_out;

    cudaFuncSetAttribute(deepar_kernel,
                         cudaFuncAttributeMaxDynamicSharedMemorySize, SM_BYTES);

    deepar_kernel<<<NCTA, TPB, SM_BYTES>>>(
        hist, fut, emb_W, emb_b,
        W_ih0, W_hh0, b_ih0, b_hh0,
        W_ih1, W_hh1, b_ih1, b_hh1,
        head_W, head_b, out);
}

// round 13
// speedup vs baseline: 2.8352x; 2.5684x over previous
#include <cuda_runtime.h>
#include <cuda_bf16.h>
#include <stdint.h>

// DeepAR forward: 2-layer LSTM (H=64), T=383, 16384 seqs.
// Persistent 296 CTAs x 256 thr. Matvecs on tensor cores via
// mma.sync.m16n8k16 bf16 (plain sm_103 target: no tcgen05 available).
// Weights resident in A-fragments (registers); h carried bf16 in smem;
// fp32 accum; in-register epilogue w/ MUFU.TANH; cell update fp32.

#define TPB 256
#define SEQ 56
#define GRP 14
#define NCTA 296
#define NSTEP 383
#define NSEQ_TOT 16384
#define PH 72            // hT pitch (bf16 elems; 144B rows, B-load conflict-free)
#define PG 260           // G pitch (floats; STS/LDS conflict-free)

// smem byte offsets
#define OB_HT0 0                 // hT0 [64][PH] bf16 = 9216
#define OB_HT1 9216              // hT1            = 9216
#define OB_G   18432             // G [64][PG] f32 = 66560
#define OB_H1F 84992             // h1 fp32 [56][66] = 14784
#define OB_XS  99776             // x staging 2 x [5][64] f32 = 2560
#define OB_CF  102336            // coeffs [256][8] f32 = 8192
#define OB_HW  110528            // head_W 128 f
#define OB_HB  111040            // head_b 2 f
#define SM_BYTES 111104

static __device__ __forceinline__ uint32_t pkbf(float lo, float hi) {
    __nv_bfloat162 v = __floats2bfloat162_rn(lo, hi);
    return *reinterpret_cast<uint32_t*>(&v);
}
static __device__ __forceinline__ float tanh_(float x) {
    float r; asm("tanh.approx.f32 %0, %1;" : "=f"(r) : "f"(x)); return r;
}
static __device__ __forceinline__ float sigm_(float x) {
    return fmaf(0.5f, tanh_(0.5f * x), 0.5f);
}

#define MMA(dd, aa, b0, b1)                                                   \
    asm volatile(                                                             \
        "mma.sync.aligned.m16n8k16.row.col.f32.bf16.bf16.f32 "                \
        "{%0,%1,%2,%3}, {%4,%5,%6,%7}, {%8,%9}, {%0,%1,%2,%3};"               \
        : "+f"((dd)[0]), "+f"((dd)[1]), "+f"((dd)[2]), "+f"((dd)[3])          \
        : "r"((aa)[0]), "r"((aa)[1]), "r"((aa)[2]), "r"((aa)[3]),             \
          "r"(b0), "r"(b1))

static __device__ __forceinline__ void ldx(const float* __restrict__ hist,
                                           const float* __restrict__ fut,
                                           int myb, int myn, int t,
                                           float& x0, float& x1, float& x2,
                                           float& x3, float& x4) {
    const float* s1 = (t < 336)
        ? hist + (((size_t)myb * 336 + t) * 512 + myn) * 5
        : fut  + (((size_t)myb * 48 + (t - 336)) * 512 + myn) * 5;
    int tc = t + 1;
    const float* s2 = (tc < 336)
        ? hist + (((size_t)myb * 336 + tc) * 512 + myn) * 5
        : fut  + (((size_t)myb * 48 + (tc - 336)) * 512 + myn) * 5;
    x0 = s1[0];
    x1 = s2[1]; x2 = s2[2]; x3 = s2[3]; x4 = s2[4];
}

extern "C" __global__ void __launch_bounds__(TPB, 1)
deepar_kernel(const float* __restrict__ hist, const float* __restrict__ fut,
              const float* __restrict__ emb_W, const float* __restrict__ emb_b,
              const float* __restrict__ W_ih0, const float* __restrict__ W_hh0,
              const float* __restrict__ b_ih0, const float* __restrict__ b_hh0,
              const float* __restrict__ W_ih1, const float* __restrict__ W_hh1,
              const float* __restrict__ b_ih1, const float* __restrict__ b_hh1,
              const float* __restrict__ head_W, const float* __restrict__ head_b,
              float* __restrict__ out)
{
    extern __shared__ char sm[];
    float* G   = (float*)(sm + OB_G);
    float* h1f = (float*)(sm + OB_H1F);
    float* xs  = (float*)(sm + OB_XS);
    float* cf  = (float*)(sm + OB_CF);

    const int tid = threadIdx.x;
    const int wid = tid >> 5, lane = tid & 31;
    const int g = lane >> 2, tq = lane & 3;
    const int mbase = wid * 32;           // this warp's 32 gate rows
    const int gate = mbase >> 6;          // 0:i 1:f 2:g 3:o (uniform per warp)
    // cell role
    const int u = tid & 63, sg = tid >> 6;
    const int sbase = sg * GRP;
    const int gbase = blockIdx.x * SEQ;

    // ---- init: per-row coefficients (row = tid) ----
    {
        const float* wr = W_ih0 + tid * 36;
        float a = 0.f, bb = 0.f;
#pragma unroll
        for (int e = 0; e < 32; e++) {
            a  = fmaf(wr[e], emb_W[e], a);
            bb = fmaf(wr[e], emb_b[e], bb);
        }
        float* c = cf + tid * 8;
        c[0] = a;                                   // v1
        c[1] = bb + b_ih0[tid] + b_hh0[tid];        // v2
        c[2] = wr[32]; c[3] = wr[33]; c[4] = wr[34]; c[5] = wr[35];
        c[6] = b_ih1[tid] + b_hh1[tid];             // b1
        c[7] = 0.f;
    }
    // zero both h tiles (h(-1)=0, plus n-pad rows 56..63)
    for (int e = tid; e < 4608; e += TPB) ((uint32_t*)(sm + OB_HT0))[e] = 0;
    if (tid < 128) ((float*)(sm + OB_HW))[tid] = head_W[tid];
    if (tid < 2)   ((float*)(sm + OB_HB))[tid] = head_b[tid];

    // ---- A fragments (weights) -> registers, once ----
    uint32_t a0f[2][4][4];     // W_hh0
    uint32_t a1f[2][8][4];     // [kt 0..3]=W_ih1, [4..7]=W_hh1
#pragma unroll
    for (int mt = 0; mt < 2; mt++) {
#pragma unroll
        for (int kt = 0; kt < 4; kt++) {
            int r0 = mbase + mt * 16 + g, r1 = r0 + 8;
            int k0 = kt * 16 + tq * 2, k2 = k0 + 8;
            a0f[mt][kt][0] = pkbf(W_hh0[r0 * 64 + k0], W_hh0[r0 * 64 + k0 + 1]);
            a0f[mt][kt][1] = pkbf(W_hh0[r1 * 64 + k0], W_hh0[r1 * 64 + k0 + 1]);
            a0f[mt][kt][2] = pkbf(W_hh0[r0 * 64 + k2], W_hh0[r0 * 64 + k2 + 1]);
            a0f[mt][kt][3] = pkbf(W_hh0[r1 * 64 + k2], W_hh0[r1 * 64 + k2 + 1]);
            a1f[mt][kt][0] = pkbf(W_ih1[r0 * 64 + k0], W_ih1[r0 * 64 + k0 + 1]);
            a1f[mt][kt][1] = pkbf(W_ih1[r1 * 64 + k0], W_ih1[r1 * 64 + k0 + 1]);
            a1f[mt][kt][2] = pkbf(W_ih1[r0 * 64 + k2], W_ih1[r0 * 64 + k2 + 1]);
            a1f[mt][kt][3] = pkbf(W_ih1[r1 * 64 + k2], W_ih1[r1 * 64 + k2 + 1]);
            a1f[mt][kt + 4][0] = pkbf(W_hh1[r0 * 64 + k0], W_hh1[r0 * 64 + k0 + 1]);
            a1f[mt][kt + 4][1] = pkbf(W_hh1[r1 * 64 + k0], W_hh1[r1 * 64 + k0 + 1]);
            a1f[mt][kt + 4][2] = pkbf(W_hh1[r0 * 64 + k2], W_hh1[r0 * 64 + k2 + 1]);
            a1f[mt][kt + 4][3] = pkbf(W_hh1[r1 * 64 + k2], W_hh1[r1 * 64 + k2 + 1]);
        }
    }

    float c0[GRP], c1[GRP];
#pragma unroll
    for (int i = 0; i < GRP; i++) { c0[i] = 0.f; c1[i] = 0.f; }

    const bool duty = (u < GRP);
    const int mys = sbase + (u < GRP ? u : 0);
    int mygs = gbase + mys; if (mygs > NSEQ_TOT - 1) mygs = NSEQ_TOT - 1;
    const int myb = mygs >> 9, myn = mygs & 511;

    float xr0, xr1, xr2, xr3, xr4;
    if (duty) {
        float a0, a1, a2, a3, a4;
        ldx(hist, fut, myb, myn, 0, a0, a1, a2, a3, a4);
        xs[mys] = a0; xs[64 + mys] = a1; xs[128 + mys] = a2;
        xs[192 + mys] = a3; xs[256 + mys] = a4;
        ldx(hist, fut, myb, myn, 1, xr0, xr1, xr2, xr3, xr4);
    }
    __syncthreads();   // coeffs, zero h, x(0) visible

    for (int t = 0; t < NSTEP; t++) {
        const bool notlast = (t + 1 < NSTEP);
        float d[2][8][4];

        // ---- MMA L0: D = Whh0 @ h0T ----
#pragma unroll
        for (int mt = 0; mt < 2; mt++)
#pragma unroll
            for (int nt = 0; nt < 8; nt++)
#pragma unroll
                for (int q = 0; q < 4; q++) d[mt][nt][q] = 0.f;
#pragma unroll
        for (int kt = 0; kt < 4; kt++) {
#pragma unroll
            for (int nt = 0; nt < 8; nt++) {
                const char* bp = sm + OB_HT0
                    + ((nt * 8 + g) * PH + kt * 16 + tq * 2) * 2;
                uint32_t b0 = *(const uint32_t*)bp;
                uint32_t b1 = *(const uint32_t*)(bp + 16);
                MMA(d[0][nt], a0f[0][kt], b0, b1);
                MMA(d[1][nt], a0f[1][kt], b0, b1);
            }
        }

        // ---- epilogue L0: + x-part + v2; activate; -> G ----
        {
            const float* xc = xs + (t & 1) * 320;
            float4 CA[4], CB[4];
#pragma unroll
            for (int ri = 0; ri < 4; ri++) {
                int r = mbase + (ri >> 1) * 16 + (ri & 1) * 8 + g;
                CA[ri] = *(const float4*)(cf + r * 8);
                CB[ri] = *(const float4*)(cf + r * 8 + 4);
            }
#pragma unroll
            for (int nt = 0; nt < 8; nt++) {
                int n0 = nt * 8 + tq * 2;
                float2 X0 = *(const float2*)(xc + n0);
                float2 X1 = *(const float2*)(xc + 64 + n0);
                float2 X2 = *(const float2*)(xc + 128 + n0);
                float2 X3 = *(const float2*)(xc + 192 + n0);
                float2 X4 = *(const float2*)(xc + 256 + n0);
#pragma unroll
                for (int ri = 0; ri < 4; ri++) {
                    int mt = ri >> 1, rr = ri & 1;
                    int r = mbase + mt * 16 + rr * 8 + g;
#pragma unroll
                    for (int c = 0; c < 2; c++) {
                        float v = d[mt][nt][rr * 2 + c] + CA[ri].y;
                        v = fmaf(c ? X0.y : X0.x, CA[ri].x, v);
                        v = fmaf(c ? X1.y : X1.x, CA[ri].z, v);
                        v = fmaf(c ? X2.y : X2.x, CA[ri].w, v);
                        v = fmaf(c ? X3.y : X3.x, CB[ri].x, v);
                        v = fmaf(c ? X4.y : X4.x, CB[ri].y, v);
                        G[(n0 + c) * PG + r] = (gate == 2) ? tanh_(v) : sigm_(v);
                    }
                }
            }
        }
        __syncthreads();   // bar1: G(L0) ready; hT0 B-reads done

        // ---- cell L0: update c0, write h0 bf16 -> hT0 ----
#pragma unroll
        for (int j = 0; j < GRP; j++) {
            int s = sbase + j;
            float I  = G[s * PG + u];
            float F  = G[s * PG + 64 + u];
            float Gg = G[s * PG + 128 + u];
            float O  = G[s * PG + 192 + u];
            float c = fmaf(F, c0[j], I * Gg);
            c0[j] = c;
            float h = O * tanh_(c);
            *(__nv_bfloat16*)(sm + OB_HT0 + (s * PH + u) * 2) =
                __float2bfloat16(h);
        }
        __syncthreads();   // bar2: new hT0 visible

        // ---- MMA L1: D = Wih1 @ h0new + Whh1 @ h1old ----
#pragma unroll
        for (int mt = 0; mt < 2; mt++)
#pragma unroll
            for (int nt = 0; nt < 8; nt++)
#pragma unroll
                for (int q = 0; q < 4; q++) d[mt][nt][q] = 0.f;
#pragma unroll
        for (int kt = 0; kt < 4; kt++) {
#pragma unroll
            for (int nt = 0; nt < 8; nt++) {
                const char* bp = sm + OB_HT0
                    + ((nt * 8 + g) * PH + kt * 16 + tq * 2) * 2;
                uint32_t b0 = *(const uint32_t*)bp;
                uint32_t b1 = *(const uint32_t*)(bp + 16);
                MMA(d[0][nt], a1f[0][kt], b0, b1);
                MMA(d[1][nt], a1f[1][kt], b0, b1);
            }
        }
#pragma unroll
        for (int kt = 0; kt < 4; kt++) {
#pragma unroll
            for (int nt = 0; nt < 8; nt++) {
                const char* bp = sm + OB_HT1
                    + ((nt * 8 + g) * PH + kt * 16 + tq * 2) * 2;
                uint32_t b0 = *(const uint32_t*)bp;
                uint32_t b1 = *(const uint32_t*)(bp + 16);
                MMA(d[0][nt], a1f[0][kt + 4], b0, b1);
                MMA(d[1][nt], a1f[1][kt + 4], b0, b1);
            }
        }

        // stage x(t+1); prefetch x(t+2)
        if (duty && notlast) {
            float* xp = xs + ((t + 1) & 1) * 320;
            xp[mys] = xr0; xp[64 + mys] = xr1; xp[128 + mys] = xr2;
            xp[192 + mys] = xr3; xp[256 + mys] = xr4;
        }
        if (duty && t + 2 < NSTEP)
            ldx(hist, fut, myb, myn, t + 2, xr0, xr1, xr2, xr3, xr4);

        // ---- epilogue L1: + b1; activate; -> G ----
        {
            float b1c[4];
#pragma unroll
            for (int ri = 0; ri < 4; ri++) {
                int r = mbase + (ri >> 1) * 16 + (ri & 1) * 8 + g;
                b1c[ri] = cf[r * 8 + 6];
            }
#pragma unroll
            for (int nt = 0; nt < 8; nt++) {
                int n0 = nt * 8 + tq * 2;
#pragma unroll
                for (int ri = 0; ri < 4; ri++) {
                    int mt = ri >> 1, rr = ri & 1;
                    int r = mbase + mt * 16 + rr * 8 + g;
#pragma unroll
                    for (int c = 0; c < 2; c++) {
                        float v = d[mt][nt][rr * 2 + c] + b1c[ri];
                        G[(n0 + c) * PG + r] = (gate == 2) ? tanh_(v) : sigm_(v);
                    }
                }
            }
        }
        __syncthreads();   // bar3: G(L1) ready; hT1 B-reads done

        // ---- cell L1: update c1, write h1 bf16 + fp32 ----
#pragma unroll
        for (int j = 0; j < GRP; j++) {
            int s = sbase + j;
            float I  = G[s * PG + u];
            float F  = G[s * PG + 64 + u];
            float Gg = G[s * PG + 128 + u];
            float O  = G[s * PG + 192 + u];
            float c = fmaf(F, c1[j], I * Gg);
            c1[j] = c;
            float h = O * tanh_(c);
            *(__nv_bfloat16*)(sm + OB_HT1 + (s * PH + u) * 2) =
                __float2bfloat16(h);
            h1f[s * 66 + u] = h;
        }
        __syncthreads();   // bar4: hT1 + h1f visible

        // ---- head (last 48 steps) ----
        if (t >= 335 && duty) {
            const float* hr = h1f + mys * 66;
            const float* hwp = (const float*)(sm + OB_HW);
            float p0 = ((const float*)(sm + OB_HB))[0];
            float p1 = ((const float*)(sm + OB_HB))[1];
#pragma unroll 8
            for (int j = 0; j < 64; j++) {
                float v = fmaxf(hr[j], 0.f);
                p0 = fmaf(v, hwp[j], p0);
                p1 = fmaf(v, hwp[64 + j], p1);
            }
            float sp = (p1 > 15.f) ? p1 : log1pf(__expf(p1));
            ((float2*)out)[((size_t)myb * 48 + (t - 335)) * 512 + myn] =
                make_float2(p0, sp);
        }
    }
}

extern "C" void kernel_launch(void* const* d_in, const int* in_sizes, int n_in,
                              void* d_out, int out_size) {
    (void)in_sizes; (void)n_in; (void)out_size;
    cudaFuncSetAttribute(deepar_kernel,
                         cudaFuncAttributeMaxDynamicSharedMemorySize, SM_BYTES);
    deepar_kernel<<<NCTA, TPB, SM_BYTES>>>(
        (const float*)d_in[0], (const float*)d_in[1],
        (const float*)d_in[2], (const float*)d_in[3],
        (const float*)d_in[4], (const float*)d_in[5],
        (const float*)d_in[6], (const float*)d_in[7],
        (const float*)d_in[8], (const float*)d_in[9],
        (const float*)d_in[10], (const float*)d_in[11],
        (const float*)d_in[12], (const float*)d_in[13],
        (float*)d_out);
}

// round 14
// speedup vs baseline: 2.9124x; 1.0272x over previous
#include <cuda_runtime.h>
#include <cuda_bf16.h>
#include <cuda_fp16.h>
#include <stdint.h>

// DeepAR forward, tensor-core (mma.sync m16n8k16 bf16), persistent 296x256.
// R13: fused-phase pipeline -> 2 barriers/step. Per iteration t:
//   phase C: cell L1(t-1) + cell L0(t) (gates from fp16 G1/G0); stage x(t+1)
//   bar A
//   phase M: ALL MMAs: dA = Wih1@h0(t)+Whh1@h1(t-1), dB = Whh0@h0(t) [192/warp,
//            shared hT0 B-frags]; head(t-1); epiA->G1(t); epiB(x(t+1))->G0(t+1)
//   bar B
// Weights bf16 in smem via ldmatrix.x4; gates fp16 in smem; h bf16; c fp32.

#define TPB 256
#define SEQ 56
#define GRP 14
#define NCTA 296
#define NSTEP 383
#define NSEQ_TOT 16384
#define PWT 72           // weight tile pitch (halfwords)
#define PHT 72           // hT pitch (halfwords)
#define PGW 33           // G pitch in 32-bit words (66 halfwords)

// smem byte offsets
#define OB_W0   0          // Whh0 [256][PWT] bf16 = 36864
#define OB_WI1  36864
#define OB_WH1  73728
#define OB_G0   110592     // G fp16 [256 rows][PGW words] = 33792
#define OB_G1   144384
#define OB_HT0  178176     // hT [64 n][PHT] bf16 = 9216
#define OB_HT1  187392
#define OB_H1F  196608     // h1 fp32 [56][66] = 14784
#define OB_XS   211392     // 2 x [5][64] f32 = 2560
#define OB_CF   213952     // coeffs [256][8] f32 = 8192
#define OB_HW   222144     // head_W 128 f
#define OB_HB   222656     // head_b
#define SM_BYTES 222720

static __device__ __forceinline__ uint32_t s2u(const void* p) {
    uint32_t a;
    asm("{\n.reg .u64 t;\ncvta.to.shared.u64 t, %1;\ncvt.u32.u64 %0, t;\n}"
        : "=r"(a) : "l"(p));
    return a;
}
static __device__ __forceinline__ float tanh_(float x) {
    float r; asm("tanh.approx.f32 %0, %1;" : "=f"(r) : "f"(x)); return r;
}
static __device__ __forceinline__ float sigm_(float x) {
    return fmaf(0.5f, tanh_(0.5f * x), 0.5f);
}

#define MMA(dd, aa, b0, b1)                                                   \
    asm volatile(                                                             \
        "mma.sync.aligned.m16n8k16.row.col.f32.bf16.bf16.f32 "                \
        "{%0,%1,%2,%3}, {%4,%5,%6,%7}, {%8,%9}, {%0,%1,%2,%3};"               \
        : "+f"((dd)[0]), "+f"((dd)[1]), "+f"((dd)[2]), "+f"((dd)[3])          \
        : "r"((aa)[0]), "r"((aa)[1]), "r"((aa)[2]), "r"((aa)[3]),             \
          "r"(b0), "r"(b1))

#define LDSM4(f, a)                                                           \
    asm volatile("ldmatrix.sync.aligned.m8n8.x4.shared.b16 "                  \
                 "{%0,%1,%2,%3}, [%4];"                                       \
                 : "=r"((f)[0]), "=r"((f)[1]), "=r"((f)[2]), "=r"((f)[3])     \
                 : "r"(a))

static __device__ __forceinline__ void ldx(const float* __restrict__ hist,
                                           const float* __restrict__ fut,
                                           int myb, int myn, int t,
                                           float& x0, float& x1, float& x2,
                                           float& x3, float& x4) {
    const float* s1 = (t < 336)
        ? hist + (((size_t)myb * 336 + t) * 512 + myn) * 5
        : fut  + (((size_t)myb * 48 + (t - 336)) * 512 + myn) * 5;
    int tc = t + 1;
    const float* s2 = (tc < 336)
        ? hist + (((size_t)myb * 336 + tc) * 512 + myn) * 5
        : fut  + (((size_t)myb * 48 + (tc - 336)) * 512 + myn) * 5;
    x0 = s1[0];
    x1 = s2[1]; x2 = s2[2]; x3 = s2[3]; x4 = s2[4];
}

extern "C" __global__ void __launch_bounds__(TPB, 1)
deepar_kernel(const float* __restrict__ hist, const float* __restrict__ fut,
              const float* __restrict__ emb_W, const float* __restrict__ emb_b,
              const float* __restrict__ W_ih0, const float* __restrict__ W_hh0,
              const float* __restrict__ b_ih0, const float* __restrict__ b_hh0,
              const float* __restrict__ W_ih1, const float* __restrict__ W_hh1,
              const float* __restrict__ b_ih1, const float* __restrict__ b_hh1,
              const float* __restrict__ head_W, const float* __restrict__ head_b,
              float* __restrict__ out)
{
    extern __shared__ char sm[];
    float* h1f = (float*)(sm + OB_H1F);
    float* xs  = (float*)(sm + OB_XS);
    float* cf  = (float*)(sm + OB_CF);
    __half2* G0w = (__half2*)(sm + OB_G0);
    __half2* G1w = (__half2*)(sm + OB_G1);

    const int tid = threadIdx.x;
    const int wid = tid >> 5, lane = tid & 31;
    const int g = lane >> 2, tq = lane & 3;
    const int mbase = wid * 32;
    const int gate = wid >> 1;            // 0:i 1:f 2:g 3:o (uniform per warp)
    // cell role
    const int u = tid & 63, sg = tid >> 6;
    const int sbase = sg * GRP;
    const int sb2 = sbase >> 1;           // GRP=14 even -> sbase even
    const int gbase = blockIdx.x * SEQ;

    // ---- init: weights -> bf16 smem tiles [r][PWT] ----
    for (int e = tid; e < 256 * 64; e += TPB) {
        int r = e >> 6, k = e & 63;
        int o = r * PWT + k;
        ((__nv_bfloat16*)(sm + OB_W0))[o]  = __float2bfloat16(W_hh0[e]);
        ((__nv_bfloat16*)(sm + OB_WI1))[o] = __float2bfloat16(W_ih1[e]);
        ((__nv_bfloat16*)(sm + OB_WH1))[o] = __float2bfloat16(W_hh1[e]);
    }
    // zero both hT tiles (h(-1)=0 + n-pad rows)
    for (int e = tid; e < 4608; e += TPB) ((uint32_t*)(sm + OB_HT0))[e] = 0;
    if (tid < 128) ((float*)(sm + OB_HW))[tid] = head_W[tid];
    if (tid < 2)   ((float*)(sm + OB_HB))[tid] = head_b[tid];

    // per-row coefficients (row = tid): v1,v2,wc0..3,b1
    {
        const float* wr = W_ih0 + tid * 36;
        float a = 0.f, bb = 0.f;
#pragma unroll
        for (int e = 0; e < 32; e++) {
            a  = fmaf(wr[e], emb_W[e], a);
            bb = fmaf(wr[e], emb_b[e], bb);
        }
        float* c = cf + tid * 8;
        c[0] = a;
        c[1] = bb + b_ih0[tid] + b_hh0[tid];
        c[2] = wr[32]; c[3] = wr[33]; c[4] = wr[34]; c[5] = wr[35];
        c[6] = b_ih1[tid] + b_hh1[tid];
        c[7] = 0.f;
    }

    float c0[GRP], c1[GRP];
#pragma unroll
    for (int i = 0; i < GRP; i++) { c0[i] = 0.f; c1[i] = 0.f; }

    const bool duty = (u < GRP);
    const int mys = sbase + (u < GRP ? u : 0);
    int mygs = gbase + mys; if (mygs > NSEQ_TOT - 1) mygs = NSEQ_TOT - 1;
    const int myb = mygs >> 9, myn = mygs & 511;

    // LDSM lane-constant byte offset within a weight matrix
    const uint32_t aoff =
        (uint32_t)(((mbase + (lane & 15)) * PWT + ((lane >> 4) << 3)) * 2);
    const uint32_t uW0  = s2u(sm + OB_W0)  + aoff;
    const uint32_t uWI1 = s2u(sm + OB_WI1) + aoff;
    const uint32_t uWH1 = s2u(sm + OB_WH1) + aoff;

    // stage x(0) into buf0; prefetch x(1)
    float xr0, xr1, xr2, xr3, xr4;
    if (duty) {
        float a0, a1, a2, a3, a4;
        ldx(hist, fut, myb, myn, 0, a0, a1, a2, a3, a4);
        xs[mys] = a0; xs[64 + mys] = a1; xs[128 + mys] = a2;
        xs[192 + mys] = a3; xs[256 + mys] = a4;
        ldx(hist, fut, myb, myn, 1, xr0, xr1, xr2, xr3, xr4);
    }
    __syncthreads();

    // ---- prologue: G0(0) = act(v2 + xpart(x(0)))  (h0(-1)=0) ----
    {
        const float* xc = xs;   // buf0
#pragma unroll
        for (int ri = 0; ri < 4; ri++) {
            int r = mbase + (ri >> 1) * 16 + (ri & 1) * 8 + g;
            float4 CA = *(const float4*)(cf + r * 8);
            float4 CB = *(const float4*)(cf + r * 8 + 4);
#pragma unroll
            for (int nt = 0; nt < 8; nt++) {
                int n0 = nt * 8 + tq * 2;
                float2 X0 = *(const float2*)(xc + n0);
                float2 X1 = *(const float2*)(xc + 64 + n0);
                float2 X2 = *(const float2*)(xc + 128 + n0);
                float2 X3 = *(const float2*)(xc + 192 + n0);
                float2 X4 = *(const float2*)(xc + 256 + n0);
                float va = CA.y, vb = CA.y;
                va = fmaf(X0.x, CA.x, va); vb = fmaf(X0.y, CA.x, vb);
                va = fmaf(X1.x, CA.z, va); vb = fmaf(X1.y, CA.z, vb);
                va = fmaf(X2.x, CA.w, va); vb = fmaf(X2.y, CA.w, vb);
                va = fmaf(X3.x, CB.x, va); vb = fmaf(X3.y, CB.x, vb);
                va = fmaf(X4.x, CB.y, va); vb = fmaf(X4.y, CB.y, vb);
                float aa = (gate == 2) ? tanh_(va) : sigm_(va);
                float ab = (gate == 2) ? tanh_(vb) : sigm_(vb);
                G0w[r * PGW + nt * 4 + tq] = __floats2half2_rn(aa, ab);
            }
        }
    }
    __syncthreads();   // G0(0) visible ("bar B" of iteration -1)

    for (int t = 0; t < NSTEP; t++) {
        // ================= phase C: cell updates =================
        if (t > 0) {
            // cell L1(t-1): G1 -> c1, h1 -> hT1 bf16 + h1f fp32
#pragma unroll
            for (int p = 0; p < 7; p++) {
                int s0 = sbase + 2 * p;
                __half2 I2 = G1w[u * PGW + sb2 + p];
                __half2 F2 = G1w[(64 + u) * PGW + sb2 + p];
                __half2 g2 = G1w[(128 + u) * PGW + sb2 + p];
                __half2 O2 = G1w[(192 + u) * PGW + sb2 + p];
                float ca = fmaf(__low2float(F2), c1[2 * p],
                                __low2float(I2) * __low2float(g2));
                float cb = fmaf(__high2float(F2), c1[2 * p + 1],
                                __high2float(I2) * __high2float(g2));
                c1[2 * p] = ca; c1[2 * p + 1] = cb;
                float ha = __low2float(O2) * tanh_(ca);
                float hb = __high2float(O2) * tanh_(cb);
                ((__nv_bfloat16*)(sm + OB_HT1))[s0 * PHT + u] = __float2bfloat16(ha);
                ((__nv_bfloat16*)(sm + OB_HT1))[(s0 + 1) * PHT + u] = __float2bfloat16(hb);
                h1f[s0 * 66 + u] = ha;
                h1f[(s0 + 1) * 66 + u] = hb;
            }
        }
        // cell L0(t): G0 -> c0, h0 -> hT0 bf16
#pragma unroll
        for (int p = 0; p < 7; p++) {
            int s0 = sbase + 2 * p;
            __half2 I2 = G0w[u * PGW + sb2 + p];
            __half2 F2 = G0w[(64 + u) * PGW + sb2 + p];
            __half2 g2 = G0w[(128 + u) * PGW + sb2 + p];
            __half2 O2 = G0w[(192 + u) * PGW + sb2 + p];
            float ca = fmaf(__low2float(F2), c0[2 * p],
                            __low2float(I2) * __low2float(g2));
            float cb = fmaf(__high2float(F2), c0[2 * p + 1],
                            __high2float(I2) * __high2float(g2));
            c0[2 * p] = ca; c0[2 * p + 1] = cb;
            ((__nv_bfloat16*)(sm + OB_HT0))[s0 * PHT + u] =
                __float2bfloat16(__low2float(O2) * tanh_(ca));
            ((__nv_bfloat16*)(sm + OB_HT0))[(s0 + 1) * PHT + u] =
                __float2bfloat16(__high2float(O2) * tanh_(cb));
        }
        // stage x(t+1)
        if (duty && t + 1 < NSTEP) {
            float* xp = xs + ((t + 1) & 1) * 320;
            xp[mys] = xr0; xp[64 + mys] = xr1; xp[128 + mys] = xr2;
            xp[192 + mys] = xr3; xp[256 + mys] = xr4;
        }
        __syncthreads();   // bar A: hT0(t), hT1(t-1), h1f(t-1), x(t+1) visible

        // ================= phase M: all MMAs + epilogues =================
        if (duty && t + 2 < NSTEP)
            ldx(hist, fut, myb, myn, t + 2, xr0, xr1, xr2, xr3, xr4);

        float dA[2][8][4], dB[2][8][4];
#pragma unroll
        for (int mt = 0; mt < 2; mt++)
#pragma unroll
            for (int nt = 0; nt < 8; nt++)
#pragma unroll
                for (int q = 0; q < 4; q++) { dA[mt][nt][q] = 0.f; dB[mt][nt][q] = 0.f; }

        // dA += Wih1 @ h0(t), dB += Whh0 @ h0(t)  (shared hT0 B-frags)
#pragma unroll
        for (int kt = 0; kt < 4; kt++) {
            uint32_t fI0[4], fI1[4], fH0[4], fH1[4];
            LDSM4(fI0, uWI1 + kt * 32);
            LDSM4(fI1, uWI1 + 2304 + kt * 32);
            LDSM4(fH0, uW0 + kt * 32);
            LDSM4(fH1, uW0 + 2304 + kt * 32);
#pragma unroll
            for (int nt = 0; nt < 8; nt++) {
                const char* bp = sm + OB_HT0
                    + ((nt * 8 + g) * PHT + kt * 16 + tq * 2) * 2;
                uint32_t b0 = *(const uint32_t*)bp;
                uint32_t b1 = *(const uint32_t*)(bp + 16);
                MMA(dA[0][nt], fI0, b0, b1);
                MMA(dA[1][nt], fI1, b0, b1);
                MMA(dB[0][nt], fH0, b0, b1);
                MMA(dB[1][nt], fH1, b0, b1);
            }
        }
        // dA += Whh1 @ h1(t-1)
#pragma unroll
        for (int kt = 0; kt < 4; kt++) {
            uint32_t fA0[4], fA1[4];
            LDSM4(fA0, uWH1 + kt * 32);
            LDSM4(fA1, uWH1 + 2304 + kt * 32);
#pragma unroll
            for (int nt = 0; nt < 8; nt++) {
                const char* bp = sm + OB_HT1
                    + ((nt * 8 + g) * PHT + kt * 16 + tq * 2) * 2;
                uint32_t b0 = *(const uint32_t*)bp;
                uint32_t b1 = *(const uint32_t*)(bp + 16);
                MMA(dA[0][nt], fA0, b0, b1);
                MMA(dA[1][nt], fA1, b0, b1);
            }
        }

        // head(t-1) (h1f written in phase C, bar A separated)
        if (t >= 336 && duty) {
            const float* hr = h1f + mys * 66;
            const float* hwp = (const float*)(sm + OB_HW);
            float p0 = ((const float*)(sm + OB_HB))[0];
            float p1 = ((const float*)(sm + OB_HB))[1];
#pragma unroll 8
            for (int j = 0; j < 64; j++) {
                float v = fmaxf(hr[j], 0.f);
                p0 = fmaf(v, hwp[j], p0);
                p1 = fmaf(v, hwp[64 + j], p1);
            }
            float sp = (p1 > 15.f) ? p1 : log1pf(__expf(p1));
            ((float2*)out)[((size_t)myb * 48 + (t - 1 - 335)) * 512 + myn] =
                make_float2(p0, sp);
        }

        // epilogue A: G1(t) = act(dA + b1)
#pragma unroll
        for (int ri = 0; ri < 4; ri++) {
            int mt = ri >> 1, rr = ri & 1;
            int r = mbase + mt * 16 + rr * 8 + g;
            float b1v = cf[r * 8 + 6];
#pragma unroll
            for (int nt = 0; nt < 8; nt++) {
                float va = dA[mt][nt][rr * 2 + 0] + b1v;
                float vb = dA[mt][nt][rr * 2 + 1] + b1v;
                float aa = (gate == 2) ? tanh_(va) : sigm_(va);
                float ab = (gate == 2) ? tanh_(vb) : sigm_(vb);
                G1w[r * PGW + nt * 4 + tq] = __floats2half2_rn(aa, ab);
            }
        }
        // epilogue B: G0(t+1) = act(dB + v2 + xpart(x(t+1)))
        if (t + 1 < NSTEP) {
            const float* xc = xs + ((t + 1) & 1) * 320;
#pragma unroll
            for (int ri = 0; ri < 4; ri++) {
                int mt = ri >> 1, rr = ri & 1;
                int r = mbase + mt * 16 + rr * 8 + g;
                float4 CA = *(const float4*)(cf + r * 8);
                float4 CB = *(const float4*)(cf + r * 8 + 4);
#pragma unroll
                for (int nt = 0; nt < 8; nt++) {
                    int n0 = nt * 8 + tq * 2;
                    float2 X0 = *(const float2*)(xc + n0);
                    float2 X1 = *(const float2*)(xc + 64 + n0);
                    float2 X2 = *(const float2*)(xc + 128 + n0);
                    float2 X3 = *(const float2*)(xc + 192 + n0);
                    float2 X4 = *(const float2*)(xc + 256 + n0);
                    float va = dB[mt][nt][rr * 2 + 0] + CA.y;
                    float vb = dB[mt][nt][rr * 2 + 1] + CA.y;
                    va = fmaf(X0.x, CA.x, va); vb = fmaf(X0.y, CA.x, vb);
                    va = fmaf(X1.x, CA.z, va); vb = fmaf(X1.y, CA.z, vb);
                    va = fmaf(X2.x, CA.w, va); vb = fmaf(X2.y, CA.w, vb);
                    va = fmaf(X3.x, CB.x, va); vb = fmaf(X3.y, CB.x, vb);
                    va = fmaf(X4.x, CB.y, va); vb = fmaf(X4.y, CB.y, vb);
                    float aa = (gate == 2) ? tanh_(va) : sigm_(va);
                    float ab = (gate == 2) ? tanh_(vb) : sigm_(vb);
                    G0w[r * PGW + nt * 4 + tq] = __floats2half2_rn(aa, ab);
                }
            }
        }
        __syncthreads();   // bar B: G1(t), G0(t+1) visible; hT reads done
    }

    // ---- drain: cell L1(382) -> h1f; head(382) ----
#pragma unroll
    for (int p = 0; p < 7; p++) {
        int s0 = sbase + 2 * p;
        __half2 I2 = G1w[u * PGW + sb2 + p];
        __half2 F2 = G1w[(64 + u) * PGW + sb2 + p];
        __half2 g2 = G1w[(128 + u) * PGW + sb2 + p];
        __half2 O2 = G1w[(192 + u) * PGW + sb2 + p];
        float ca = fmaf(__low2float(F2), c1[2 * p],
                        __low2float(I2) * __low2float(g2));
        float cb = fmaf(__high2float(F2), c1[2 * p + 1],
                        __high2float(I2) * __high2float(g2));
        h1f[s0 * 66 + u] = __low2float(O2) * tanh_(ca);
        h1f[(s0 + 1) * 66 + u] = __high2float(O2) * tanh_(cb);
    }
    __syncthreads();
    if (duty) {
        const float* hr = h1f + mys * 66;
        const float* hwp = (const float*)(sm + OB_HW);
        float p0 = ((const float*)(sm + OB_HB))[0];
        float p1 = ((const float*)(sm + OB_HB))[1];
#pragma unroll 8
        for (int j = 0; j < 64; j++) {
            float v = fmaxf(hr[j], 0.f);
            p0 = fmaf(v, hwp[j], p0);
            p1 = fmaf(v, hwp[64 + j], p1);
        }
        float sp = (p1 > 15.f) ? p1 : log1pf(__expf(p1));
        ((float2*)out)[((size_t)myb * 48 + 47) * 512 + myn] = make_float2(p0, sp);
    }
}

extern "C" void kernel_launch(void* const* d_in, const int* in_sizes, int n_in,
                              void* d_out, int out_size) {
    (void)in_sizes; (void)n_in; (void)out_size;
    cudaFuncSetAttribute(deepar_kernel,
                         cudaFuncAttributeMaxDynamicSharedMemorySize, SM_BYTES);
    deepar_kernel<<<NCTA, TPB, SM_BYTES>>>(
        (const float*)d_in[0], (const float*)d_in[1],
        (const float*)d_in[2], (const float*)d_in[3],
        (const float*)d_in[4], (const float*)d_in[5],
        (const float*)d_in[6], (const float*)d_in[7],
        (const float*)d_in[8], (const float*)d_in[9],
        (const float*)d_in[10], (const float*)d_in[11],
        (const float*)d_in[12], (const float*)d_in[13],
        (float*)d_out);
}

// round 15
// speedup vs baseline: 5.1407x; 1.7651x over previous
#include <cuda_runtime.h>
#include <cuda_bf16.h>
#include <stdint.h>

// DeepAR forward, tensor-core mma.sync m16n8k16 bf16, persistent 296x256.
// R14: gate-interleaved A-row permutation -> warp w owns units 8w..8w+7 with
// all 4 gates; after MMA each thread holds i,f,g,o of ONE unit for its cols
// -> LSTM cell update fully in-register (c in regs), no gate smem buffer.
// x-projection folded into the L0 MMA (A k=64..68 = [v1|wc], hT0 k=64..68 =
// [prev|cov] bf16). Double-buffered hT0/hT1/h1f; 2 barriers/step; 7 n-tiles.

#define TPB 256
#define SEQ 56
#define NCTA 296
#define NSTEP 383
#define NSEQ_TOT 16384
#define PW0 88            // Whh0+x A-tile pitch (halfwords; k 0..79 used)
#define PW1 72            // Wih1/Whh1 pitch
#define PH0 88            // hT0 pitch (k 0..63 h, 64..68 x, rest 0)
#define PH1 72            // hT1 pitch

// smem byte offsets
#define OB_W0   0               // [256][PW0] bf16 = 45056
#define OB_WI1  45056           // [256][PW1] bf16 = 36864
#define OB_WH1  81920           // 36864
#define OB_HT0  118784          // 2 x [64][PH0] bf16 (11264 each)
#define HT0_SZ  11264
#define OB_HT1  141312          // 2 x [64][PH1] bf16 (9216 each)
#define HT1_SZ  9216
#define OB_H1F  159744          // 2 x [56][66] f32 (14784 each)
#define H1F_SZ  14784
#define OB_HW   189312          // head_W 128 f
#define OB_HB   189824          // head_b 2 f
#define SM_BYTES 189952

static __device__ __forceinline__ uint32_t s2u(const void* p) {
    uint32_t a;
    asm("{\n.reg .u64 t;\ncvta.to.shared.u64 t, %1;\ncvt.u32.u64 %0, t;\n}"
        : "=r"(a) : "l"(p));
    return a;
}
static __device__ __forceinline__ float tanh_(float x) {
    float r; asm("tanh.approx.f32 %0, %1;" : "=f"(r) : "f"(x)); return r;
}
static __device__ __forceinline__ float sigm_(float x) {
    return fmaf(0.5f, tanh_(0.5f * x), 0.5f);
}

#define MMA(dd, aa, b0, b1)                                                   \
    asm volatile(                                                             \
        "mma.sync.aligned.m16n8k16.row.col.f32.bf16.bf16.f32 "                \
        "{%0,%1,%2,%3}, {%4,%5,%6,%7}, {%8,%9}, {%0,%1,%2,%3};"               \
        : "+f"((dd)[0]), "+f"((dd)[1]), "+f"((dd)[2]), "+f"((dd)[3])          \
        : "r"((aa)[0]), "r"((aa)[1]), "r"((aa)[2]), "r"((aa)[3]),             \
          "r"(b0), "r"(b1))

#define LDSM4(f, a)                                                           \
    asm volatile("ldmatrix.sync.aligned.m8n8.x4.shared.b16 "                  \
                 "{%0,%1,%2,%3}, [%4];"                                       \
                 : "=r"((f)[0]), "=r"((f)[1]), "=r"((f)[2]), "=r"((f)[3])     \
                 : "r"(a))

// permuted A-row index for (gate G, unit u)
static __device__ __forceinline__ int prow(int G, int u) {
    return ((u >> 3) << 5) | ((G >> 1) << 4) | ((G & 1) << 3) | (u & 7);
}

static __device__ __forceinline__ void ldx(const float* __restrict__ hist,
                                           const float* __restrict__ fut,
                                           int myb, int myn, int t,
                                           float& x0, float& x1, float& x2,
                                           float& x3, float& x4) {
    const float* s1 = (t < 336)
        ? hist + (((size_t)myb * 336 + t) * 512 + myn) * 5
        : fut  + (((size_t)myb * 48 + (t - 336)) * 512 + myn) * 5;
    int tc = t + 1;
    const float* s2 = (tc < 336)
        ? hist + (((size_t)myb * 336 + tc) * 512 + myn) * 5
        : fut  + (((size_t)myb * 48 + (tc - 336)) * 512 + myn) * 5;
    x0 = s1[0];
    x1 = s2[1]; x2 = s2[2]; x3 = s2[3]; x4 = s2[4];
}

extern "C" __global__ void __launch_bounds__(TPB, 1)
deepar_kernel(const float* __restrict__ hist, const float* __restrict__ fut,
              const float* __restrict__ emb_W, const float* __restrict__ emb_b,
              const float* __restrict__ W_ih0, const float* __restrict__ W_hh0,
              const float* __restrict__ b_ih0, const float* __restrict__ b_hh0,
              const float* __restrict__ W_ih1, const float* __restrict__ W_hh1,
              const float* __restrict__ b_ih1, const float* __restrict__ b_hh1,
              const float* __restrict__ head_W, const float* __restrict__ head_b,
              float* __restrict__ out)
{
    extern __shared__ char sm[];
    const int tid = threadIdx.x;
    const int wid = tid >> 5, lane = tid & 31;
    const int gid = lane >> 2, tq = lane & 3;
    const int mbase = wid * 32;
    const int un = (wid << 3) + gid;        // this thread's hidden unit

    const bool duty = (tid < SEQ);
    const int mys = duty ? tid : 0;
    const int gbase = blockIdx.x * SEQ;
    int mygs = gbase + mys; if (mygs > NSEQ_TOT - 1) mygs = NSEQ_TOT - 1;
    const int myb = mygs >> 9, myn = mygs & 511;

    // ---- zero all tiles (weights pads, hT bufs) ----
    for (int e = tid; e < 159744 / 4; e += TPB) ((uint32_t*)sm)[e] = 0;
    __syncthreads();

    // ---- weights k<64, permuted rows ----
    __nv_bfloat16* w0  = (__nv_bfloat16*)(sm + OB_W0);
    __nv_bfloat16* wi1 = (__nv_bfloat16*)(sm + OB_WI1);
    __nv_bfloat16* wh1 = (__nv_bfloat16*)(sm + OB_WH1);
    for (int e = tid; e < 256 * 64; e += TPB) {
        int r = e >> 6, k = e & 63;
        int p = prow(r >> 6, r & 63);
        w0[p * PW0 + k]  = __float2bfloat16(W_hh0[e]);
        wi1[p * PW1 + k] = __float2bfloat16(W_ih1[e]);
        wh1[p * PW1 + k] = __float2bfloat16(W_hh1[e]);
    }
    // x-projection columns of the L0 A-tile: k=64 -> v1, k=65..68 -> wc
    {
        int r = tid;                       // one gate-row per thread
        int p = prow(r >> 6, r & 63);
        const float* wr = W_ih0 + r * 36;
        float a = 0.f;
#pragma unroll
        for (int e = 0; e < 32; e++) a = fmaf(wr[e], emb_W[e], a);
        w0[p * PW0 + 64] = __float2bfloat16(a);
#pragma unroll
        for (int k = 0; k < 4; k++)
            w0[p * PW0 + 65 + k] = __float2bfloat16(wr[32 + k]);
    }
    if (tid < 128) ((float*)(sm + OB_HW))[tid] = head_W[tid];
    if (tid < 2)   ((float*)(sm + OB_HB))[tid] = head_b[tid];

    // ---- per-thread fp32 biases for this unit's 4 gates ----
    float v2g[4], b1g[4];
#pragma unroll
    for (int G = 0; G < 4; G++) {
        int r = G * 64 + un;
        const float* wr = W_ih0 + r * 36;
        float bb = 0.f;
#pragma unroll
        for (int e = 0; e < 32; e++) bb = fmaf(wr[e], emb_b[e], bb);
        v2g[G] = bb + b_ih0[r] + b_hh0[r];
        b1g[G] = b_ih1[r] + b_hh1[r];
    }

    float c0[14], c1[14];
#pragma unroll
    for (int i = 0; i < 14; i++) { c0[i] = 0.f; c1[i] = 0.f; }

    // stage x(0) into hT0 buf0 (k=64..68)
    if (duty) {
        float a0, a1, a2, a3, a4;
        ldx(hist, fut, myb, myn, 0, a0, a1, a2, a3, a4);
        __nv_bfloat16* xb = (__nv_bfloat16*)(sm + OB_HT0);
        xb[mys * PH0 + 64] = __float2bfloat16(a0);
        xb[mys * PH0 + 65] = __float2bfloat16(a1);
        xb[mys * PH0 + 66] = __float2bfloat16(a2);
        xb[mys * PH0 + 67] = __float2bfloat16(a3);
        xb[mys * PH0 + 68] = __float2bfloat16(a4);
    }
    __syncthreads();

    // LDSM lane-constant addresses
    const uint32_t aoff0 =
        (uint32_t)(((mbase + (lane & 15)) * PW0 + ((lane >> 4) << 3)) * 2);
    const uint32_t aoff1 =
        (uint32_t)(((mbase + (lane & 15)) * PW1 + ((lane >> 4) << 3)) * 2);
    const uint32_t uW0 = s2u(sm + OB_W0) + aoff0;
    const uint32_t uWI = s2u(sm + OB_WI1) + aoff1;
    const uint32_t uWH = s2u(sm + OB_WH1) + aoff1;

    for (int t = 0; t < NSTEP; t++) {
        const int rd = t & 1, wr = rd ^ 1;
        const char* ht0r = sm + OB_HT0 + rd * HT0_SZ;
        char*       ht0w = sm + OB_HT0 + wr * HT0_SZ;
        const char* ht1r = sm + OB_HT1 + rd * HT1_SZ;
        char*       ht1w = sm + OB_HT1 + wr * HT1_SZ;
        float*      h1fw = (float*)(sm + OB_H1F + wr * H1F_SZ);

        const bool pf = duty && (t + 1 < NSTEP);
        float xr0, xr1, xr2, xr3, xr4;
        if (pf) ldx(hist, fut, myb, myn, t + 1, xr0, xr1, xr2, xr3, xr4);

        // ===== MMA0: pre0 = [Whh0 | v1,wc] @ [h0(t-1) ; x(t)] =====
        float dd[2][7][4];
#pragma unroll
        for (int mt = 0; mt < 2; mt++)
#pragma unroll
            for (int nt = 0; nt < 7; nt++)
#pragma unroll
                for (int q = 0; q < 4; q++) dd[mt][nt][q] = 0.f;
#pragma unroll
        for (int kt = 0; kt < 5; kt++) {
            uint32_t f0[4], f1[4];
            LDSM4(f0, uW0 + kt * 32);
            LDSM4(f1, uW0 + 16 * PW0 * 2 + kt * 32);
#pragma unroll
            for (int nt = 0; nt < 7; nt++) {
                const char* bp = ht0r
                    + ((nt * 8 + gid) * PH0 + kt * 16 + tq * 2) * 2;
                uint32_t b0 = *(const uint32_t*)bp;
                uint32_t b1 = *(const uint32_t*)(bp + 16);
                MMA(dd[0][nt], f0, b0, b1);
                MMA(dd[1][nt], f1, b0, b1);
            }
        }
        // in-register cell L0: thread = unit un, 14 seq-cols
#pragma unroll
        for (int nt = 0; nt < 7; nt++) {
#pragma unroll
            for (int c = 0; c < 2; c++) {
                float I = sigm_(dd[0][nt][c]     + v2g[0]);
                float F = sigm_(dd[0][nt][2 + c] + v2g[1]);
                float G = tanh_(dd[1][nt][c]     + v2g[2]);
                float O = sigm_(dd[1][nt][2 + c] + v2g[3]);
                int idx = nt * 2 + c;
                float cc = fmaf(F, c0[idx], I * G);
                c0[idx] = cc;
                float h = O * tanh_(cc);
                ((__nv_bfloat16*)ht0w)[(nt * 8 + tq * 2 + c) * PH0 + un] =
                    __float2bfloat16(h);
            }
        }
        __syncthreads();   // bar A: h0(t) visible

        // ===== MMA1: pre1 = Wih1 @ h0(t) + Whh1 @ h1(t-1) =====
#pragma unroll
        for (int mt = 0; mt < 2; mt++)
#pragma unroll
            for (int nt = 0; nt < 7; nt++)
#pragma unroll
                for (int q = 0; q < 4; q++) dd[mt][nt][q] = 0.f;
#pragma unroll
        for (int kt = 0; kt < 4; kt++) {
            uint32_t f0[4], f1[4];
            LDSM4(f0, uWI + kt * 32);
            LDSM4(f1, uWI + 16 * PW1 * 2 + kt * 32);
#pragma unroll
            for (int nt = 0; nt < 7; nt++) {
                const char* bp = ht0w
                    + ((nt * 8 + gid) * PH0 + kt * 16 + tq * 2) * 2;
                uint32_t b0 = *(const uint32_t*)bp;
                uint32_t b1 = *(const uint32_t*)(bp + 16);
                MMA(dd[0][nt], f0, b0, b1);
                MMA(dd[1][nt], f1, b0, b1);
            }
        }
#pragma unroll
        for (int kt = 0; kt < 4; kt++) {
            uint32_t f0[4], f1[4];
            LDSM4(f0, uWH + kt * 32);
            LDSM4(f1, uWH + 16 * PW1 * 2 + kt * 32);
#pragma unroll
            for (int nt = 0; nt < 7; nt++) {
                const char* bp = ht1r
                    + ((nt * 8 + gid) * PH1 + kt * 16 + tq * 2) * 2;
                uint32_t b0 = *(const uint32_t*)bp;
                uint32_t b1 = *(const uint32_t*)(bp + 16);
                MMA(dd[0][nt], f0, b0, b1);
                MMA(dd[1][nt], f1, b0, b1);
            }
        }
        // stage x(t+1) into hT0[wr] k=64..68 (disjoint from MMA1's k<64 reads)
        if (pf) {
            __nv_bfloat16* xb = (__nv_bfloat16*)ht0w;
            xb[mys * PH0 + 64] = __float2bfloat16(xr0);
            xb[mys * PH0 + 65] = __float2bfloat16(xr1);
            xb[mys * PH0 + 66] = __float2bfloat16(xr2);
            xb[mys * PH0 + 67] = __float2bfloat16(xr3);
            xb[mys * PH0 + 68] = __float2bfloat16(xr4);
        }
        // in-register cell L1
#pragma unroll
        for (int nt = 0; nt < 7; nt++) {
#pragma unroll
            for (int c = 0; c < 2; c++) {
                float I = sigm_(dd[0][nt][c]     + b1g[0]);
                float F = sigm_(dd[0][nt][2 + c] + b1g[1]);
                float G = tanh_(dd[1][nt][c]     + b1g[2]);
                float O = sigm_(dd[1][nt][2 + c] + b1g[3]);
                int idx = nt * 2 + c;
                float cc = fmaf(F, c1[idx], I * G);
                c1[idx] = cc;
                float h = O * tanh_(cc);
                int n = nt * 8 + tq * 2 + c;
                ((__nv_bfloat16*)ht1w)[n * PH1 + un] = __float2bfloat16(h);
                h1fw[n * 66 + un] = h;
            }
        }
        __syncthreads();   // bar B: h1(t), h1f(t), x(t+1) visible

        // ---- head(t) (last 48 steps) ----
        if (t >= 335 && duty) {
            const float* hr = h1fw + mys * 66;
            const float* hwp = (const float*)(sm + OB_HW);
            float p0 = ((const float*)(sm + OB_HB))[0];
            float p1 = ((const float*)(sm + OB_HB))[1];
#pragma unroll 8
            for (int j = 0; j < 64; j++) {
                float v = fmaxf(hr[j], 0.f);
                p0 = fmaf(v, hwp[j], p0);
                p1 = fmaf(v, hwp[64 + j], p1);
            }
            float sp = (p1 > 15.f) ? p1 : log1pf(__expf(p1));
            ((float2*)out)[((size_t)myb * 48 + (t - 335)) * 512 + myn] =
                make_float2(p0, sp);
        }
    }
}

extern "C" void kernel_launch(void* const* d_in, const int* in_sizes, int n_in,
                              void* d_out, int out_size) {
    (void)in_sizes; (void)n_in; (void)out_size;
    cudaFuncSetAttribute(deepar_kernel,
                         cudaFuncAttributeMaxDynamicSharedMemorySize, SM_BYTES);
    deepar_kernel<<<NCTA, TPB, SM_BYTES>>>(
        (const float*)d_in[0], (const float*)d_in[1],
        (const float*)d_in[2], (const float*)d_in[3],
        (const float*)d_in[4], (const float*)d_in[5],
        (const float*)d_in[6], (const float*)d_in[7],
        (const float*)d_in[8], (const float*)d_in[9],
        (const float*)d_in[10], (const float*)d_in[11],
        (const float*)d_in[12], (const float*)d_in[13],
        (float*)d_out);
}